// round 10
// baseline (speedup 1.0000x reference)
#include <cuda_runtime.h>
#include <cuda_bf16.h>
#include <cstdint>

#define DEPTH 32
#define NODES 512
#define NPAR 8
#define NB 32
#define HID 128
#define ROWS_PER_B 16385
#define STRB 272            // smem tile row stride bytes (136 bf16); 272 = 17*16
#define NTHREADS 512
#define ZROW 16385          // permanent zero row of g_buf (slot 0 padding)
#define NFLAGS 16386

// ---------------- device statics ----------------
__device__ float g_cpre[DEPTH * NODES * HID];
__device__ float g_W1bT[64 * HID];
__device__ __align__(16) __nv_bfloat16 g_w1hi[HID * HID];  // [n][k]
__device__ __align__(16) __nv_bfloat16 g_w1lo[HID * HID];
__device__ __align__(16) __nv_bfloat16 g_w2hi[HID * HID];
__device__ __align__(16) __nv_bfloat16 g_w2lo[HID * HID];
// node-major value mirror + 1 zero row: g_buf[g_row][batch][128], g_row = slot-1
__device__ float g_buf[(size_t)(2 + DEPTH * NODES) * NB * HID];
// per-row ready flags (reset each run by prep_kernel)
__device__ unsigned g_flag[NFLAGS];

// ---------------- helpers ----------------
__device__ __forceinline__ uint32_t smem_u32(const void* p) {
    uint32_t a;
    asm("{ .reg .u64 t; cvta.to.shared.u64 t, %1; cvt.u32.u64 %0, t; }" : "=r"(a) : "l"(p));
    return a;
}
__device__ __forceinline__ void ldsm4(uint32_t addr, uint32_t r[4]) {
    asm volatile("ldmatrix.sync.aligned.m8n8.x4.shared.b16 {%0,%1,%2,%3}, [%4];"
        : "=r"(r[0]), "=r"(r[1]), "=r"(r[2]), "=r"(r[3]) : "r"(addr));
}
__device__ __forceinline__ void mma16816(float c[4], const uint32_t a[4],
                                         uint32_t b0, uint32_t b1) {
    asm volatile("mma.sync.aligned.m16n8k16.row.col.f32.bf16.bf16.f32 "
        "{%0,%1,%2,%3}, {%4,%5,%6,%7}, {%8,%9}, {%0,%1,%2,%3};"
        : "+f"(c[0]), "+f"(c[1]), "+f"(c[2]), "+f"(c[3])
        : "r"(a[0]), "r"(a[1]), "r"(a[2]), "r"(a[3]), "r"(b0), "r"(b1));
}
__device__ __forceinline__ void cp_async16(uint32_t smem_addr, const void* gptr) {
    asm volatile("cp.async.cg.shared.global [%0], [%1], 16;"
        :: "r"(smem_addr), "l"(gptr) : "memory");
}
__device__ __forceinline__ void cp_commit() {
    asm volatile("cp.async.commit_group;" ::: "memory");
}
__device__ __forceinline__ void cp_wait_all() {
    asm volatile("cp.async.wait_group 0;" ::: "memory");
}
__device__ __forceinline__ void split2(float a, float b, uint32_t& hi, uint32_t& lo) {
    __nv_bfloat16 ah = __float2bfloat16(a), bh = __float2bfloat16(b);
    __nv_bfloat16 al = __float2bfloat16(a - __bfloat162float(ah));
    __nv_bfloat16 bl = __float2bfloat16(b - __bfloat162float(bh));
    hi = (uint32_t)__bfloat16_as_ushort(ah) | ((uint32_t)__bfloat16_as_ushort(bh) << 16);
    lo = (uint32_t)__bfloat16_as_ushort(al) | ((uint32_t)__bfloat16_as_ushort(bl) << 16);
}
__device__ __forceinline__ float2 unsplit2(uint32_t h, uint32_t l) {
    float ax = __bfloat162float(__ushort_as_bfloat16((unsigned short)(h & 0xFFFF)));
    float ay = __bfloat162float(__ushort_as_bfloat16((unsigned short)(h >> 16)));
    float bx = __bfloat162float(__ushort_as_bfloat16((unsigned short)(l & 0xFFFF)));
    float by = __bfloat162float(__ushort_as_bfloat16((unsigned short)(l >> 16)));
    return make_float2(ax + bx, ay + by);
}

// ---------------- smem layout ----------------
#define TILE_B  (128 * STRB)              // 34816
#define SM_W2HI 0
#define SM_W2LO (1 * TILE_B)
#define SM_HHI  (2 * TILE_B)              // W1hi (cp.async), then H hi
#define SM_HLO  (3 * TILE_B)              // W1lo (cp.async), then H lo
#define SM_AHI  (4 * TILE_B)
#define SM_ALO  (5 * TILE_B)
#define SM_PIDX (6 * TILE_B)              // 128 B
#define SM_CPRE (6 * TILE_B + 128)        // 2048 B
#define SM_B2   (6 * TILE_B + 128 + 2048) // 512 B
#define SMEM_TOTAL (6 * TILE_B + 128 + 2048 + 512)

// fused 3-term split GEMM for a 32x32 warp tile:
// acc += Ahi*Bhi + Alo*Bhi + Ahi*Blo  (K=128)
__device__ __forceinline__ void gemm3(uint32_t AhiB, uint32_t AloB,
                                      uint32_t BhiB, uint32_t BloB,
                                      int r0, int c0, int lane,
                                      float acc[2][4][4]) {
    const uint32_t rsel = (uint32_t)(lane & 15);
    const uint32_t ksel = (uint32_t)(lane >> 4) * 16;
    const uint32_t aoff = (r0 + rsel) * STRB + ksel;
    const uint32_t boff = (c0 + rsel) * STRB + ksel;
    uint32_t ah0 = AhiB + aoff, ah1 = ah0 + 16 * STRB;
    uint32_t al0 = AloB + aoff, al1 = al0 + 16 * STRB;
    uint32_t bh0 = BhiB + boff, bh1 = bh0 + 16 * STRB;
    uint32_t bl0 = BloB + boff, bl1 = bl0 + 16 * STRB;
#pragma unroll
    for (int kc = 0; kc < 8; kc++) {
        const uint32_t kb = kc * 32;
        uint32_t Ah0[4], Ah1[4], Al0[4], Al1[4];
        uint32_t Bh0[4], Bh1[4], Bl0[4], Bl1[4];
        ldsm4(ah0 + kb, Ah0); ldsm4(ah1 + kb, Ah1);
        ldsm4(bh0 + kb, Bh0); ldsm4(bh1 + kb, Bh1);
        ldsm4(al0 + kb, Al0); ldsm4(al1 + kb, Al1);
        ldsm4(bl0 + kb, Bl0); ldsm4(bl1 + kb, Bl1);
        mma16816(acc[0][0], Ah0, Bh0[0], Bh0[2]);
        mma16816(acc[0][1], Ah0, Bh0[1], Bh0[3]);
        mma16816(acc[0][2], Ah0, Bh1[0], Bh1[2]);
        mma16816(acc[0][3], Ah0, Bh1[1], Bh1[3]);
        mma16816(acc[1][0], Ah1, Bh0[0], Bh0[2]);
        mma16816(acc[1][1], Ah1, Bh0[1], Bh0[3]);
        mma16816(acc[1][2], Ah1, Bh1[0], Bh1[2]);
        mma16816(acc[1][3], Ah1, Bh1[1], Bh1[3]);
        mma16816(acc[0][0], Al0, Bh0[0], Bh0[2]);
        mma16816(acc[0][1], Al0, Bh0[1], Bh0[3]);
        mma16816(acc[0][2], Al0, Bh1[0], Bh1[2]);
        mma16816(acc[0][3], Al0, Bh1[1], Bh1[3]);
        mma16816(acc[1][0], Al1, Bh0[0], Bh0[2]);
        mma16816(acc[1][1], Al1, Bh0[1], Bh0[3]);
        mma16816(acc[1][2], Al1, Bh1[0], Bh1[2]);
        mma16816(acc[1][3], Al1, Bh1[1], Bh1[3]);
        mma16816(acc[0][0], Ah0, Bl0[0], Bl0[2]);
        mma16816(acc[0][1], Ah0, Bl0[1], Bl0[3]);
        mma16816(acc[0][2], Ah0, Bl1[0], Bl1[2]);
        mma16816(acc[0][3], Ah0, Bl1[1], Bl1[3]);
        mma16816(acc[1][0], Ah1, Bl0[0], Bl0[2]);
        mma16816(acc[1][1], Ah1, Bl0[1], Bl0[3]);
        mma16816(acc[1][2], Ah1, Bl1[0], Bl1[2]);
        mma16816(acc[1][3], Ah1, Bl1[1], Bl1[3]);
    }
}

// ---------------- prep ----------------
__global__ void prep_kernel(const float* __restrict__ emb,
                            const float* __restrict__ W1,
                            const float* __restrict__ W2,
                            float* __restrict__ out) {
    int n = blockIdx.x, tid = threadIdx.x;  // 128 x 256
    for (int k = tid; k < 192; k += 256) {
        float v = W1[n * 192 + k];
        if (k < 128) {
            __nv_bfloat16 h = __float2bfloat16(v);
            g_w1hi[n * HID + k] = h;
            g_w1lo[n * HID + k] = __float2bfloat16(v - __bfloat162float(h));
        } else {
            g_W1bT[(k - 128) * HID + n] = v;
        }
    }
    for (int k = tid; k < 128; k += 256) {
        float v = W2[n * HID + k];
        __nv_bfloat16 h = __float2bfloat16(v);
        g_w2hi[n * HID + k] = h;
        g_w2lo[n * HID + k] = __float2bfloat16(v - __bfloat162float(h));
    }
    int g = n * 256 + tid;
    if (g < NB * HID) {
        int b = g >> 7, c = g & 127;
        out[(size_t)b * ROWS_PER_B * HID + c] = emb[g];
        g_buf[(size_t)b * HID + c] = emb[g];      // g_row 0 = root
    }
    if (n == 0) {
        float* zr = g_buf + (size_t)ZROW * NB * HID;
        for (int i = tid; i < NB * HID; i += 256) zr[i] = 0.f;
        for (int i = tid; i < NFLAGS; i += 256)
            g_flag[i] = (i == 0 || i == ZROW) ? 1u : 0u;
    }
}

// ---------------- c_pre = W1b @ ne + b1 ----------------
__global__ __launch_bounds__(256) void cpre_kernel(const float* __restrict__ emb_table,
                                                   const float* __restrict__ b1) {
    __shared__ float sne[32][64];
    __shared__ float sw[64][128];
    int tid = threadIdx.x;
    int row0 = blockIdx.x * 32;
    for (int i = tid; i < 32 * 64; i += 256) {
        int r = i >> 6, e = i & 63;
        sne[r][e] = emb_table[(size_t)(2 + row0 + r) * 64 + e];
    }
    for (int i = tid; i < 64 * 128; i += 256)
        sw[i >> 7][i & 127] = g_W1bT[i];
    __syncthreads();
    int c = tid & 127;
    int rh = (tid >> 7) * 16;
    float acc[16];
    float bv = b1[c];
#pragma unroll
    for (int rr = 0; rr < 16; rr++) acc[rr] = bv;
    for (int k = 0; k < 64; k++) {
        float w = sw[k][c];
#pragma unroll
        for (int rr = 0; rr < 16; rr++) acc[rr] += sne[rh + rr][k] * w;
    }
#pragma unroll
    for (int rr = 0; rr < 16; rr++)
        g_cpre[(size_t)(row0 + rh + rr) * HID + c] = acc[rr];
}

// issue async W1 -> H region (8 x 16B per thread; no registers held)
__device__ __forceinline__ void w1_cp_async(uint32_t sb, int tid) {
    // hi: 2048 16B-chunks, lo: 2048
    const char* srch = (const char*)g_w1hi;
    const char* srcl = (const char*)g_w1lo;
#pragma unroll
    for (int j = 0; j < 4; j++) {
        int i = tid + j * NTHREADS;          // 0..2047
        int r = i >> 4, q = i & 15;          // row, 16B chunk
        uint32_t dst = (uint32_t)r * STRB + q * 16;
        cp_async16(sb + SM_HHI + dst, srch + r * 256 + q * 16);
        cp_async16(sb + SM_HLO + dst, srcl + r * 256 + q * 16);
    }
    cp_commit();
}

// ---------------- persistent DAG kernel (flag-synchronized, async W1) ----------------
__global__ __launch_bounds__(NTHREADS, 1)
void dag_kernel(float* __restrict__ out, const int* __restrict__ pidx,
                const float* __restrict__ b2) {
    extern __shared__ char smc[];
    const uint32_t sb = smem_u32(smc);
    const int tid = threadIdx.x;
    const int wid = tid >> 5, lane = tid & 31;
    const int n0 = blockIdx.x * 4;
    const int* s_pidx = (const int*)(smc + SM_PIDX);

    // one-time: W2 tiles + b2 + depth-0 W1/pidx/cpre
    {
        const uint2* w2h = (const uint2*)g_w2hi;
        const uint2* w2l = (const uint2*)g_w2lo;
        const uint2* w1h = (const uint2*)g_w1hi;
        const uint2* w1l = (const uint2*)g_w1lo;
        for (int i = tid; i < 128 * 32; i += NTHREADS) {
            int r = i >> 5, q = i & 31;
            uint32_t off = (uint32_t)r * STRB + q * 8;
            *(uint2*)(smc + SM_W2HI + off) = w2h[i];
            *(uint2*)(smc + SM_W2LO + off) = w2l[i];
            *(uint2*)(smc + SM_HHI + off) = w1h[i];
            *(uint2*)(smc + SM_HLO + off) = w1l[i];
        }
        if (tid < 128) ((float*)(smc + SM_B2))[tid] = b2[tid];
        if (tid < 32)
            ((int*)(smc + SM_PIDX))[tid] = pidx[(n0 + (tid >> 3)) * NPAR + (tid & 7)];
        if (tid < 512) ((float*)(smc + SM_CPRE))[tid] = g_cpre[(size_t)n0 * HID + tid];
    }
    __syncthreads();

    for (int d = 0; d < DEPTH; d++) {
        // ---- gather: wait on this node's parent flags, then branchless sum ----
        {
            const int nnw = wid >> 2;           // node handled by this warp
            const int bbase = (wid & 3) * 8;    // batch base
            int prow;
            if (lane < NPAR) {
                int s = s_pidx[nnw * NPAR + lane];
                prow = s ? (s - 1) : ZROW;
                volatile unsigned* f = &g_flag[prow];
                while (*f == 0u) __nanosleep(64);
            }
            __syncwarp();
            __threadfence();   // acquire: parent rows now visible
            const float* pb[NPAR];
#pragma unroll
            for (int p = 0; p < NPAR; p++) {
                int row = __shfl_sync(0xFFFFFFFFu, prow, p);
                pb[p] = g_buf + (size_t)row * (NB * HID) + lane * 4;
            }
#pragma unroll
            for (int rr = 0; rr < 8; rr++) {
                int b = bbase + rr;
                float x = 0.f, y = 0.f, z = 0.f, w = 0.f;
#pragma unroll
                for (int p = 0; p < NPAR; p++) {
                    float4 v = *(const float4*)(pb[p] + (size_t)b * HID);
                    x += v.x; y += v.y; z += v.z; w += v.w;
                }
                int r = nnw * 32 + b;
                uint32_t h0, l0, h1, l1;
                split2(x, y, h0, l0);
                split2(z, w, h1, l1);
                uint32_t o = (uint32_t)r * STRB + lane * 8;
                *(uint32_t*)(smc + SM_AHI + o) = h0;
                *(uint32_t*)(smc + SM_AHI + o + 4) = h1;
                *(uint32_t*)(smc + SM_ALO + o) = l0;
                *(uint32_t*)(smc + SM_ALO + o + 4) = l1;
            }
        }
        cp_wait_all();     // W1 tiles for this depth landed (no-op at d=0)
        __syncthreads();   // A tiles + W1 visible to all

        const int nn = wid & 3;
        const int r0 = nn * 32;
        const int c0 = (wid >> 2) * 32;
        const int tq = lane >> 2;
        const int tc = (lane & 3) * 2;
        const float* s_cpre = (const float*)(smc + SM_CPRE);
        const float* s_b2 = (const float*)(smc + SM_B2);

        float acc[2][4][4];
#pragma unroll
        for (int mt = 0; mt < 2; mt++)
#pragma unroll
            for (int nt = 0; nt < 4; nt++)
#pragma unroll
                for (int q = 0; q < 4; q++) acc[mt][nt][q] = 0.f;

        // ---- GEMM1 (fused 3 terms): A x W1 (W1 in H region) ----
        gemm3(sb + SM_AHI, sb + SM_ALO, sb + SM_HHI, sb + SM_HLO, r0, c0, lane, acc);
        __syncthreads();  // everyone done reading W1 before H overwrite

        // ---- relu(D1 + cpre) -> split -> H region ----
#pragma unroll
        for (int mt = 0; mt < 2; mt++) {
#pragma unroll
            for (int nt = 0; nt < 4; nt++) {
                int c = c0 + nt * 8 + tc;
                float cp0 = s_cpre[nn * HID + c], cp1 = s_cpre[nn * HID + c + 1];
                float v0 = fmaxf(acc[mt][nt][0] + cp0, 0.f);
                float v1 = fmaxf(acc[mt][nt][1] + cp1, 0.f);
                float v2 = fmaxf(acc[mt][nt][2] + cp0, 0.f);
                float v3 = fmaxf(acc[mt][nt][3] + cp1, 0.f);
                uint32_t hi, lo;
                uint32_t oA = (uint32_t)(r0 + mt * 16 + tq) * STRB + c * 2;
                uint32_t oB = oA + 8 * STRB;
                split2(v0, v1, hi, lo);
                *(uint32_t*)(smc + SM_HHI + oA) = hi;
                *(uint32_t*)(smc + SM_HLO + oA) = lo;
                split2(v2, v3, hi, lo);
                *(uint32_t*)(smc + SM_HHI + oB) = hi;
                *(uint32_t*)(smc + SM_HLO + oB) = lo;
            }
        }
        __syncthreads();

#pragma unroll
        for (int mt = 0; mt < 2; mt++)
#pragma unroll
            for (int nt = 0; nt < 4; nt++)
#pragma unroll
                for (int q = 0; q < 4; q++) acc[mt][nt][q] = 0.f;

        // ---- GEMM2 (fused 3 terms): H x W2 ----
        gemm3(sb + SM_HHI, sb + SM_HLO, sb + SM_W2HI, sb + SM_W2LO, r0, c0, lane, acc);
        __syncthreads();   // all H reads done -> H region free for async W1'

        // ---- kick next depth's W1 (async), pidx, cpre; then epilogue ----
        if (d + 1 < DEPTH) {
            w1_cp_async(sb, tid);
            if (tid < 32)
                ((int*)(smc + SM_PIDX))[tid] =
                    pidx[((d + 1) * NODES + n0 + (tid >> 3)) * NPAR + (tid & 7)];
            if (tid < 512)
                ((float*)(smc + SM_CPRE))[tid] =
                    g_cpre[(size_t)((d + 1) * NODES + n0) * HID + tid];
        }

        // ---- epilogue: pv from A tiles, out = pv + D2 + b2 ----
        {
            const int orow = 1 + d * NODES + n0 + nn;  // out row == g_buf row
#pragma unroll
            for (int mt = 0; mt < 2; mt++) {
#pragma unroll
                for (int half = 0; half < 2; half++) {
                    int b = mt * 16 + tq + half * 8;
                    int rA = r0 + b;
                    float* po = out + ((size_t)b * ROWS_PER_B + orow) * HID;
                    float* pg = g_buf + ((size_t)orow * NB + b) * HID;
#pragma unroll
                    for (int nt = 0; nt < 4; nt++) {
                        int c = c0 + nt * 8 + tc;
                        uint32_t off = (uint32_t)rA * STRB + c * 2;
                        float2 pvv = unsplit2(*(const uint32_t*)(smc + SM_AHI + off),
                                              *(const uint32_t*)(smc + SM_ALO + off));
                        float2 o;
                        o.x = acc[mt][nt][half * 2 + 0] + s_b2[c] + pvv.x;
                        o.y = acc[mt][nt][half * 2 + 1] + s_b2[c + 1] + pvv.y;
                        *(float2*)(po + c) = o;
                        *(float2*)(pg + c) = o;
                    }
                }
            }
        }
        __syncthreads();   // all threads' g_buf stores done (CTA-visible)

        // ---- publish this CTA's 4 node rows (early; cp.async still in flight) ----
        if (tid < 4) {
            __threadfence();   // cumulative release of all observed stores
            *(volatile unsigned*)&g_flag[1 + d * NODES + n0 + tid] = 1u;
        }
    }
}

extern "C" void kernel_launch(void* const* d_in, const int* in_sizes, int n_in,
                              void* d_out, int out_size) {
    const float* embedding  = (const float*)d_in[0];
    const float* emb_table  = (const float*)d_in[1];
    const float* W1         = (const float*)d_in[2];
    const float* b1         = (const float*)d_in[3];
    const float* W2         = (const float*)d_in[4];
    const float* b2         = (const float*)d_in[5];
    const int*   parent_idx = (const int*)d_in[6];
    float* out = (float*)d_out;
    (void)in_sizes; (void)n_in; (void)out_size;

    cudaFuncSetAttribute(dag_kernel,
                         cudaFuncAttributeMaxDynamicSharedMemorySize, SMEM_TOTAL);

    prep_kernel<<<128, 256>>>(embedding, W1, W2, out);
    cpre_kernel<<<DEPTH * NODES / 32, 256>>>(emb_table, b1);
    dag_kernel<<<128, NTHREADS, SMEM_TOTAL>>>(out, parent_idx, b2);
}

// round 11
// speedup vs baseline: 1.0585x; 1.0585x over previous
#include <cuda_runtime.h>
#include <cuda_bf16.h>
#include <cstdint>

#define DEPTH 32
#define NODES 512
#define NPAR 8
#define NB 32
#define HID 128
#define ROWS_PER_B 16385
#define STRB 272            // smem tile row stride bytes (136 bf16)
#define NTHREADS 512
#define ZROW 16385          // permanent zero row of g_buf (slot 0 padding)
#define NFLAGS 16386

// ---------------- device statics ----------------
__device__ float g_cpre[DEPTH * NODES * HID];
__device__ float g_W1bT[64 * HID];
__device__ __nv_bfloat16 g_w1hi[HID * HID], g_w1lo[HID * HID];  // [n][k]
__device__ __nv_bfloat16 g_w2hi[HID * HID], g_w2lo[HID * HID];  // [n][k]
// node-major value mirror + 1 zero row: g_buf[g_row][batch][128], g_row = slot-1
__device__ float g_buf[(size_t)(2 + DEPTH * NODES) * NB * HID];
// per-row ready flags: 4 = ready (4 writer-warp arrivals); reset each run
__device__ unsigned g_flag[NFLAGS];

// ---------------- helpers ----------------
__device__ __forceinline__ uint32_t smem_u32(const void* p) {
    uint32_t a;
    asm("{ .reg .u64 t; cvta.to.shared.u64 t, %1; cvt.u32.u64 %0, t; }" : "=r"(a) : "l"(p));
    return a;
}
__device__ __forceinline__ void ldsm4(uint32_t addr, uint32_t r[4]) {
    asm volatile("ldmatrix.sync.aligned.m8n8.x4.shared.b16 {%0,%1,%2,%3}, [%4];"
        : "=r"(r[0]), "=r"(r[1]), "=r"(r[2]), "=r"(r[3]) : "r"(addr));
}
__device__ __forceinline__ void mma16816(float c[4], const uint32_t a[4],
                                         uint32_t b0, uint32_t b1) {
    asm volatile("mma.sync.aligned.m16n8k16.row.col.f32.bf16.bf16.f32 "
        "{%0,%1,%2,%3}, {%4,%5,%6,%7}, {%8,%9}, {%0,%1,%2,%3};"
        : "+f"(c[0]), "+f"(c[1]), "+f"(c[2]), "+f"(c[3])
        : "r"(a[0]), "r"(a[1]), "r"(a[2]), "r"(a[3]), "r"(b0), "r"(b1));
}
__device__ __forceinline__ void split2(float a, float b, uint32_t& hi, uint32_t& lo) {
    __nv_bfloat16 ah = __float2bfloat16(a), bh = __float2bfloat16(b);
    __nv_bfloat16 al = __float2bfloat16(a - __bfloat162float(ah));
    __nv_bfloat16 bl = __float2bfloat16(b - __bfloat162float(bh));
    hi = (uint32_t)__bfloat16_as_ushort(ah) | ((uint32_t)__bfloat16_as_ushort(bh) << 16);
    lo = (uint32_t)__bfloat16_as_ushort(al) | ((uint32_t)__bfloat16_as_ushort(bl) << 16);
}
__device__ __forceinline__ float2 unsplit2(uint32_t h, uint32_t l) {
    float ax = __bfloat162float(__ushort_as_bfloat16((unsigned short)(h & 0xFFFF)));
    float ay = __bfloat162float(__ushort_as_bfloat16((unsigned short)(h >> 16)));
    float bx = __bfloat162float(__ushort_as_bfloat16((unsigned short)(l & 0xFFFF)));
    float by = __bfloat162float(__ushort_as_bfloat16((unsigned short)(l >> 16)));
    return make_float2(ax + bx, ay + by);
}

// ---------------- smem layout ----------------
#define TILE_B  (128 * STRB)              // 34816
#define SM_W2HI 0
#define SM_W2LO (1 * TILE_B)
#define SM_HHI  (2 * TILE_B)              // W1hi (prefetched), then H hi
#define SM_HLO  (3 * TILE_B)              // W1lo (prefetched), then H lo
#define SM_AHI  (4 * TILE_B)
#define SM_ALO  (5 * TILE_B)
#define SM_PIDX (6 * TILE_B)              // 128 B
#define SM_CPRE (6 * TILE_B + 128)        // 2048 B
#define SM_B2   (6 * TILE_B + 128 + 2048) // 512 B
#define SMEM_TOTAL (6 * TILE_B + 128 + 2048 + 512)

// fused 3-term split GEMM for a 32x32 warp tile:
// acc += Ahi*Bhi + Alo*Bhi + Ahi*Blo  (K=128)
__device__ __forceinline__ void gemm3(uint32_t AhiB, uint32_t AloB,
                                      uint32_t BhiB, uint32_t BloB,
                                      int r0, int c0, int lane,
                                      float acc[2][4][4]) {
    const uint32_t rsel = (uint32_t)(lane & 15);
    const uint32_t ksel = (uint32_t)(lane >> 4) * 16;
    const uint32_t aoff = (r0 + rsel) * STRB + ksel;
    const uint32_t boff = (c0 + rsel) * STRB + ksel;
    uint32_t ah0 = AhiB + aoff, ah1 = ah0 + 16 * STRB;
    uint32_t al0 = AloB + aoff, al1 = al0 + 16 * STRB;
    uint32_t bh0 = BhiB + boff, bh1 = bh0 + 16 * STRB;
    uint32_t bl0 = BloB + boff, bl1 = bl0 + 16 * STRB;
#pragma unroll
    for (int kc = 0; kc < 8; kc++) {
        const uint32_t kb = kc * 32;
        uint32_t Ah0[4], Ah1[4], Al0[4], Al1[4];
        uint32_t Bh0[4], Bh1[4], Bl0[4], Bl1[4];
        ldsm4(ah0 + kb, Ah0); ldsm4(ah1 + kb, Ah1);
        ldsm4(bh0 + kb, Bh0); ldsm4(bh1 + kb, Bh1);
        ldsm4(al0 + kb, Al0); ldsm4(al1 + kb, Al1);
        ldsm4(bl0 + kb, Bl0); ldsm4(bl1 + kb, Bl1);
        mma16816(acc[0][0], Ah0, Bh0[0], Bh0[2]);
        mma16816(acc[0][1], Ah0, Bh0[1], Bh0[3]);
        mma16816(acc[0][2], Ah0, Bh1[0], Bh1[2]);
        mma16816(acc[0][3], Ah0, Bh1[1], Bh1[3]);
        mma16816(acc[1][0], Ah1, Bh0[0], Bh0[2]);
        mma16816(acc[1][1], Ah1, Bh0[1], Bh0[3]);
        mma16816(acc[1][2], Ah1, Bh1[0], Bh1[2]);
        mma16816(acc[1][3], Ah1, Bh1[1], Bh1[3]);
        mma16816(acc[0][0], Al0, Bh0[0], Bh0[2]);
        mma16816(acc[0][1], Al0, Bh0[1], Bh0[3]);
        mma16816(acc[0][2], Al0, Bh1[0], Bh1[2]);
        mma16816(acc[0][3], Al0, Bh1[1], Bh1[3]);
        mma16816(acc[1][0], Al1, Bh0[0], Bh0[2]);
        mma16816(acc[1][1], Al1, Bh0[1], Bh0[3]);
        mma16816(acc[1][2], Al1, Bh1[0], Bh1[2]);
        mma16816(acc[1][3], Al1, Bh1[1], Bh1[3]);
        mma16816(acc[0][0], Ah0, Bl0[0], Bl0[2]);
        mma16816(acc[0][1], Ah0, Bl0[1], Bl0[3]);
        mma16816(acc[0][2], Ah0, Bl1[0], Bl1[2]);
        mma16816(acc[0][3], Ah0, Bl1[1], Bl1[3]);
        mma16816(acc[1][0], Ah1, Bl0[0], Bl0[2]);
        mma16816(acc[1][1], Ah1, Bl0[1], Bl0[3]);
        mma16816(acc[1][2], Ah1, Bl1[0], Bl1[2]);
        mma16816(acc[1][3], Ah1, Bl1[1], Bl1[3]);
    }
}

// ---------------- prep ----------------
__global__ void prep_kernel(const float* __restrict__ emb,
                            const float* __restrict__ W1,
                            const float* __restrict__ W2,
                            float* __restrict__ out) {
    int n = blockIdx.x, tid = threadIdx.x;  // 128 x 256
    for (int k = tid; k < 192; k += 256) {
        float v = W1[n * 192 + k];
        if (k < 128) {
            __nv_bfloat16 h = __float2bfloat16(v);
            g_w1hi[n * HID + k] = h;
            g_w1lo[n * HID + k] = __float2bfloat16(v - __bfloat162float(h));
        } else {
            g_W1bT[(k - 128) * HID + n] = v;
        }
    }
    for (int k = tid; k < 128; k += 256) {
        float v = W2[n * HID + k];
        __nv_bfloat16 h = __float2bfloat16(v);
        g_w2hi[n * HID + k] = h;
        g_w2lo[n * HID + k] = __float2bfloat16(v - __bfloat162float(h));
    }
    int g = n * 256 + tid;
    if (g < NB * HID) {
        int b = g >> 7, c = g & 127;
        out[(size_t)b * ROWS_PER_B * HID + c] = emb[g];
        g_buf[(size_t)b * HID + c] = emb[g];      // g_row 0 = root
    }
    if (n == 0) {
        float* zr = g_buf + (size_t)ZROW * NB * HID;
        for (int i = tid; i < NB * HID; i += 256) zr[i] = 0.f;
        // flags: 4 = ready. root row ready; node rows 0.
        for (int i = tid; i < NFLAGS; i += 256)
            g_flag[i] = (i == 0 || i == ZROW) ? 4u : 0u;
    }
}

// ---------------- c_pre = W1b @ ne + b1 ----------------
__global__ __launch_bounds__(256) void cpre_kernel(const float* __restrict__ emb_table,
                                                   const float* __restrict__ b1) {
    __shared__ float sne[32][64];
    __shared__ float sw[64][128];
    int tid = threadIdx.x;
    int row0 = blockIdx.x * 32;
    for (int i = tid; i < 32 * 64; i += 256) {
        int r = i >> 6, e = i & 63;
        sne[r][e] = emb_table[(size_t)(2 + row0 + r) * 64 + e];
    }
    for (int i = tid; i < 64 * 128; i += 256)
        sw[i >> 7][i & 127] = g_W1bT[i];
    __syncthreads();
    int c = tid & 127;
    int rh = (tid >> 7) * 16;
    float acc[16];
    float bv = b1[c];
#pragma unroll
    for (int rr = 0; rr < 16; rr++) acc[rr] = bv;
    for (int k = 0; k < 64; k++) {
        float w = sw[k][c];
#pragma unroll
        for (int rr = 0; rr < 16; rr++) acc[rr] += sne[rh + rr][k] * w;
    }
#pragma unroll
    for (int rr = 0; rr < 16; rr++)
        g_cpre[(size_t)(row0 + rh + rr) * HID + c] = acc[rr];
}

// per-depth CTA-local prefetch: W1 -> H region, pidx, cpre
__device__ __forceinline__ void prefetch_depth(char* smc, const int* __restrict__ pidx,
                                               int d, int n0, int tid) {
    const uint2* w1h = (const uint2*)g_w1hi;
    const uint2* w1l = (const uint2*)g_w1lo;
    for (int i = tid; i < 128 * 32; i += NTHREADS) {
        int r = i >> 5, q = i & 31;
        uint32_t off = (uint32_t)r * STRB + q * 8;
        *(uint2*)(smc + SM_HHI + off) = w1h[i];
        *(uint2*)(smc + SM_HLO + off) = w1l[i];
    }
    if (tid < 32)
        ((int*)(smc + SM_PIDX))[tid] =
            pidx[(d * NODES + n0 + (tid >> 3)) * NPAR + (tid & 7)];
    float* s_cpre = (float*)(smc + SM_CPRE);
    const float* gc = g_cpre + (size_t)(d * NODES + n0) * HID;
    if (tid < 512) s_cpre[tid] = gc[tid];
}

// ---------------- persistent DAG kernel (per-node flag sync) ----------------
__global__ __launch_bounds__(NTHREADS, 1)
void dag_kernel(float* __restrict__ out, const int* __restrict__ pidx,
                const float* __restrict__ b2) {
    extern __shared__ char smc[];
    const uint32_t sb = smem_u32(smc);
    const int tid = threadIdx.x;
    const int wid = tid >> 5, lane = tid & 31;
    const int n0 = blockIdx.x * 4;
    const int* s_pidx = (const int*)(smc + SM_PIDX);

    // one-time: W2 tiles + b2 + depth-0 prefetch
    {
        const uint2* w2h = (const uint2*)g_w2hi;
        const uint2* w2l = (const uint2*)g_w2lo;
        for (int i = tid; i < 128 * 32; i += NTHREADS) {
            int r = i >> 5, q = i & 31;
            uint32_t off = (uint32_t)r * STRB + q * 8;
            *(uint2*)(smc + SM_W2HI + off) = w2h[i];
            *(uint2*)(smc + SM_W2LO + off) = w2l[i];
        }
        if (tid < 128) ((float*)(smc + SM_B2))[tid] = b2[tid];
        prefetch_depth(smc, pidx, 0, n0, tid);
    }
    __syncthreads();

    for (int d = 0; d < DEPTH; d++) {
        // ---- gather: wait on parent flags; skip zero parents (warp-uniform) ----
        {
            const int nnw = wid >> 2;           // node handled by this warp
            const int bbase = (wid & 3) * 8;    // batch base
            int prow = -1;
            if (lane < NPAR) {
                int s = s_pidx[nnw * NPAR + lane];
                prow = s ? (s - 1) : -1;        // -1 = padding parent, skip
                if (prow >= 0) {
                    volatile unsigned* f = &g_flag[prow];
                    while (*f < 4u) __nanosleep(64);
                }
            }
            __syncwarp();
            __threadfence();   // acquire: parent rows now visible
            float vx[8], vy[8], vz[8], vw[8];
#pragma unroll
            for (int rr = 0; rr < 8; rr++) { vx[rr] = 0.f; vy[rr] = 0.f; vz[rr] = 0.f; vw[rr] = 0.f; }
#pragma unroll
            for (int p = 0; p < NPAR; p++) {
                int row = __shfl_sync(0xFFFFFFFFu, prow, p);
                if (row < 0) continue;          // warp-uniform skip
                const float* pb = g_buf + (size_t)row * (NB * HID)
                                + (size_t)bbase * HID + lane * 4;
#pragma unroll
                for (int rr = 0; rr < 8; rr++) {
                    float4 v = *(const float4*)(pb + (size_t)rr * HID);
                    vx[rr] += v.x; vy[rr] += v.y; vz[rr] += v.z; vw[rr] += v.w;
                }
            }
#pragma unroll
            for (int rr = 0; rr < 8; rr++) {
                int r = nnw * 32 + bbase + rr;
                uint32_t h0, l0, h1, l1;
                split2(vx[rr], vy[rr], h0, l0);
                split2(vz[rr], vw[rr], h1, l1);
                uint32_t o = (uint32_t)r * STRB + lane * 8;
                *(uint32_t*)(smc + SM_AHI + o) = h0;
                *(uint32_t*)(smc + SM_AHI + o + 4) = h1;
                *(uint32_t*)(smc + SM_ALO + o) = l0;
                *(uint32_t*)(smc + SM_ALO + o + 4) = l1;
            }
        }
        __syncthreads();

        const int nn = wid & 3;
        const int r0 = nn * 32;
        const int c0 = (wid >> 2) * 32;
        const int tq = lane >> 2;
        const int tc = (lane & 3) * 2;
        const float* s_cpre = (const float*)(smc + SM_CPRE);
        const float* s_b2 = (const float*)(smc + SM_B2);

        float acc[2][4][4];
#pragma unroll
        for (int mt = 0; mt < 2; mt++)
#pragma unroll
            for (int nt = 0; nt < 4; nt++)
#pragma unroll
                for (int q = 0; q < 4; q++) acc[mt][nt][q] = 0.f;

        // ---- GEMM1 (fused 3 terms): A x W1 (W1 in H region) ----
        gemm3(sb + SM_AHI, sb + SM_ALO, sb + SM_HHI, sb + SM_HLO, r0, c0, lane, acc);
        __syncthreads();  // everyone done reading W1 before H overwrite

        // ---- relu(D1 + cpre) -> split -> H region ----
#pragma unroll
        for (int mt = 0; mt < 2; mt++) {
#pragma unroll
            for (int nt = 0; nt < 4; nt++) {
                int c = c0 + nt * 8 + tc;
                float cp0 = s_cpre[nn * HID + c], cp1 = s_cpre[nn * HID + c + 1];
                float v0 = fmaxf(acc[mt][nt][0] + cp0, 0.f);
                float v1 = fmaxf(acc[mt][nt][1] + cp1, 0.f);
                float v2 = fmaxf(acc[mt][nt][2] + cp0, 0.f);
                float v3 = fmaxf(acc[mt][nt][3] + cp1, 0.f);
                uint32_t hi, lo;
                uint32_t oA = (uint32_t)(r0 + mt * 16 + tq) * STRB + c * 2;
                uint32_t oB = oA + 8 * STRB;
                split2(v0, v1, hi, lo);
                *(uint32_t*)(smc + SM_HHI + oA) = hi;
                *(uint32_t*)(smc + SM_HLO + oA) = lo;
                split2(v2, v3, hi, lo);
                *(uint32_t*)(smc + SM_HHI + oB) = hi;
                *(uint32_t*)(smc + SM_HLO + oB) = lo;
            }
        }
        __syncthreads();

#pragma unroll
        for (int mt = 0; mt < 2; mt++)
#pragma unroll
            for (int nt = 0; nt < 4; nt++)
#pragma unroll
                for (int q = 0; q < 4; q++) acc[mt][nt][q] = 0.f;

        // ---- GEMM2 (fused 3 terms): H x W2 ----
        gemm3(sb + SM_HHI, sb + SM_HLO, sb + SM_W2HI, sb + SM_W2LO, r0, c0, lane, acc);

        // ---- epilogue: pv from A tiles, out = pv + D2 + b2 ----
        {
            const int orow = 1 + d * NODES + n0 + nn;  // out row == g_buf row
#pragma unroll
            for (int mt = 0; mt < 2; mt++) {
#pragma unroll
                for (int half = 0; half < 2; half++) {
                    int b = mt * 16 + tq + half * 8;
                    int rA = r0 + b;
                    float* po = out + ((size_t)b * ROWS_PER_B + orow) * HID;
                    float* pg = g_buf + ((size_t)orow * NB + b) * HID;
#pragma unroll
                    for (int nt = 0; nt < 4; nt++) {
                        int c = c0 + nt * 8 + tc;
                        uint32_t off = (uint32_t)rA * STRB + c * 2;
                        float2 pvv = unsplit2(*(const uint32_t*)(smc + SM_AHI + off),
                                              *(const uint32_t*)(smc + SM_ALO + off));
                        float2 o;
                        o.x = acc[mt][nt][half * 2 + 0] + s_b2[c] + pvv.x;
                        o.y = acc[mt][nt][half * 2 + 1] + s_b2[c + 1] + pvv.y;
                        *(float2*)(po + c) = o;
                        *(float2*)(pg + c) = o;
                    }
                }
            }
        }

        // ---- per-node publication: this warp's quarter of node nn is done ----
        if (d + 1 == DEPTH) break;
        __syncwarp();          // intra-warp store ordering
        __threadfence();       // cumulative release of this warp's stores
        if (lane == 0)
            atomicAdd(&g_flag[1 + d * NODES + n0 + nn], 1u);   // 4 arrivals = ready

        __syncthreads();       // all H/A reads done; A/H reusable
        prefetch_depth(smc, pidx, d + 1, n0, tid);
        __syncthreads();       // next pidx/W1/cpre visible
    }
}

extern "C" void kernel_launch(void* const* d_in, const int* in_sizes, int n_in,
                              void* d_out, int out_size) {
    const float* embedding  = (const float*)d_in[0];
    const float* emb_table  = (const float*)d_in[1];
    const float* W1         = (const float*)d_in[2];
    const float* b1         = (const float*)d_in[3];
    const float* W2         = (const float*)d_in[4];
    const float* b2         = (const float*)d_in[5];
    const int*   parent_idx = (const int*)d_in[6];
    float* out = (float*)d_out;
    (void)in_sizes; (void)n_in; (void)out_size;

    cudaFuncSetAttribute(dag_kernel,
                         cudaFuncAttributeMaxDynamicSharedMemorySize, SMEM_TOTAL);

    prep_kernel<<<128, 256>>>(embedding, W1, W2, out);
    cpre_kernel<<<DEPTH * NODES / 32, 256>>>(emb_table, b1);
    dag_kernel<<<128, NTHREADS, SMEM_TOTAL>>>(out, parent_idx, b2);
}

// round 12
// speedup vs baseline: 1.1195x; 1.0576x over previous
#include <cuda_runtime.h>
#include <cuda_bf16.h>
#include <cstdint>

#define DEPTH 32
#define NODES 512
#define NPAR 8
#define NB 32
#define HID 128
#define ROWS_PER_B 16385
#define STRB 272            // smem tile row stride bytes (136 bf16)
#define NTHREADS 512
#define ZROW 16385
#define NFLAGS 16386

// ---------------- device statics ----------------
__device__ float g_cpre[DEPTH * NODES * HID];
__device__ float g_W1bT[64 * HID];
__device__ __nv_bfloat16 g_w1hi[HID * HID], g_w1lo[HID * HID];  // [n][k]
__device__ __nv_bfloat16 g_w2hi[HID * HID], g_w2lo[HID * HID];  // [n][k]
__device__ float g_buf[(size_t)(2 + DEPTH * NODES) * NB * HID];
// per-row ready flags: 4 = ready (4 writer-warp arrivals)
__device__ unsigned g_flag[NFLAGS];

// ---------------- helpers ----------------
__device__ __forceinline__ uint32_t smem_u32(const void* p) {
    uint32_t a;
    asm("{ .reg .u64 t; cvta.to.shared.u64 t, %1; cvt.u32.u64 %0, t; }" : "=r"(a) : "l"(p));
    return a;
}
__device__ __forceinline__ void ldsm4(uint32_t addr, uint32_t r[4]) {
    asm volatile("ldmatrix.sync.aligned.m8n8.x4.shared.b16 {%0,%1,%2,%3}, [%4];"
        : "=r"(r[0]), "=r"(r[1]), "=r"(r[2]), "=r"(r[3]) : "r"(addr));
}
__device__ __forceinline__ void mma16816(float c[4], const uint32_t a[4],
                                         uint32_t b0, uint32_t b1) {
    asm volatile("mma.sync.aligned.m16n8k16.row.col.f32.bf16.bf16.f32 "
        "{%0,%1,%2,%3}, {%4,%5,%6,%7}, {%8,%9}, {%0,%1,%2,%3};"
        : "+f"(c[0]), "+f"(c[1]), "+f"(c[2]), "+f"(c[3])
        : "r"(a[0]), "r"(a[1]), "r"(a[2]), "r"(a[3]), "r"(b0), "r"(b1));
}
__device__ __forceinline__ void named_bar(int id) {
    asm volatile("bar.sync %0, 128;" :: "r"(id) : "memory");
}
__device__ __forceinline__ void split2(float a, float b, uint32_t& hi, uint32_t& lo) {
    __nv_bfloat16 ah = __float2bfloat16(a), bh = __float2bfloat16(b);
    __nv_bfloat16 al = __float2bfloat16(a - __bfloat162float(ah));
    __nv_bfloat16 bl = __float2bfloat16(b - __bfloat162float(bh));
    hi = (uint32_t)__bfloat16_as_ushort(ah) | ((uint32_t)__bfloat16_as_ushort(bh) << 16);
    lo = (uint32_t)__bfloat16_as_ushort(al) | ((uint32_t)__bfloat16_as_ushort(bl) << 16);
}

// ---------------- smem layout ----------------
#define TILE_B  (128 * STRB)              // 34816
#define SM_W1HI 0
#define SM_W1LO (1 * TILE_B)
#define SM_W2HI (2 * TILE_B)
#define SM_W2LO (3 * TILE_B)
#define SM_AHI  (4 * TILE_B)              // A tile, then H tile (per-group rows)
#define SM_ALO  (5 * TILE_B)
#define SM_B2   (6 * TILE_B)              // 512 B
#define SMEM_TOTAL (6 * TILE_B + 512)

// fused 3-term split GEMM for a 32x32 warp tile:
// acc += Ahi*Bhi + Alo*Bhi + Ahi*Blo  (K=128)
__device__ __forceinline__ void gemm3(uint32_t AhiB, uint32_t AloB,
                                      uint32_t BhiB, uint32_t BloB,
                                      int r0, int c0, int lane,
                                      float acc[2][4][4]) {
    const uint32_t rsel = (uint32_t)(lane & 15);
    const uint32_t ksel = (uint32_t)(lane >> 4) * 16;
    const uint32_t aoff = (r0 + rsel) * STRB + ksel;
    const uint32_t boff = (c0 + rsel) * STRB + ksel;
    uint32_t ah0 = AhiB + aoff, ah1 = ah0 + 16 * STRB;
    uint32_t al0 = AloB + aoff, al1 = al0 + 16 * STRB;
    uint32_t bh0 = BhiB + boff, bh1 = bh0 + 16 * STRB;
    uint32_t bl0 = BloB + boff, bl1 = bl0 + 16 * STRB;
#pragma unroll
    for (int kc = 0; kc < 8; kc++) {
        const uint32_t kb = kc * 32;
        uint32_t Ah0[4], Ah1[4], Al0[4], Al1[4];
        uint32_t Bh0[4], Bh1[4], Bl0[4], Bl1[4];
        ldsm4(ah0 + kb, Ah0); ldsm4(ah1 + kb, Ah1);
        ldsm4(bh0 + kb, Bh0); ldsm4(bh1 + kb, Bh1);
        ldsm4(al0 + kb, Al0); ldsm4(al1 + kb, Al1);
        ldsm4(bl0 + kb, Bl0); ldsm4(bl1 + kb, Bl1);
        mma16816(acc[0][0], Ah0, Bh0[0], Bh0[2]);
        mma16816(acc[0][1], Ah0, Bh0[1], Bh0[3]);
        mma16816(acc[0][2], Ah0, Bh1[0], Bh1[2]);
        mma16816(acc[0][3], Ah0, Bh1[1], Bh1[3]);
        mma16816(acc[1][0], Ah1, Bh0[0], Bh0[2]);
        mma16816(acc[1][1], Ah1, Bh0[1], Bh0[3]);
        mma16816(acc[1][2], Ah1, Bh1[0], Bh1[2]);
        mma16816(acc[1][3], Ah1, Bh1[1], Bh1[3]);
        mma16816(acc[0][0], Al0, Bh0[0], Bh0[2]);
        mma16816(acc[0][1], Al0, Bh0[1], Bh0[3]);
        mma16816(acc[0][2], Al0, Bh1[0], Bh1[2]);
        mma16816(acc[0][3], Al0, Bh1[1], Bh1[3]);
        mma16816(acc[1][0], Al1, Bh0[0], Bh0[2]);
        mma16816(acc[1][1], Al1, Bh0[1], Bh0[3]);
        mma16816(acc[1][2], Al1, Bh1[0], Bh1[2]);
        mma16816(acc[1][3], Al1, Bh1[1], Bh1[3]);
        mma16816(acc[0][0], Ah0, Bl0[0], Bl0[2]);
        mma16816(acc[0][1], Ah0, Bl0[1], Bl0[3]);
        mma16816(acc[0][2], Ah0, Bl1[0], Bl1[2]);
        mma16816(acc[0][3], Ah0, Bl1[1], Bl1[3]);
        mma16816(acc[1][0], Ah1, Bl0[0], Bl0[2]);
        mma16816(acc[1][1], Ah1, Bl0[1], Bl0[3]);
        mma16816(acc[1][2], Ah1, Bl1[0], Bl1[2]);
        mma16816(acc[1][3], Ah1, Bl1[1], Bl1[3]);
    }
}

// ---------------- prep ----------------
__global__ void prep_kernel(const float* __restrict__ emb,
                            const float* __restrict__ W1,
                            const float* __restrict__ W2,
                            float* __restrict__ out) {
    int n = blockIdx.x, tid = threadIdx.x;  // 128 x 256
    for (int k = tid; k < 192; k += 256) {
        float v = W1[n * 192 + k];
        if (k < 128) {
            __nv_bfloat16 h = __float2bfloat16(v);
            g_w1hi[n * HID + k] = h;
            g_w1lo[n * HID + k] = __float2bfloat16(v - __bfloat162float(h));
        } else {
            g_W1bT[(k - 128) * HID + n] = v;
        }
    }
    for (int k = tid; k < 128; k += 256) {
        float v = W2[n * HID + k];
        __nv_bfloat16 h = __float2bfloat16(v);
        g_w2hi[n * HID + k] = h;
        g_w2lo[n * HID + k] = __float2bfloat16(v - __bfloat162float(h));
    }
    int g = n * 256 + tid;
    if (g < NB * HID) {
        int b = g >> 7, c = g & 127;
        out[(size_t)b * ROWS_PER_B * HID + c] = emb[g];
        g_buf[(size_t)b * HID + c] = emb[g];      // g_row 0 = root
    }
    if (n == 0) {
        float* zr = g_buf + (size_t)ZROW * NB * HID;
        for (int i = tid; i < NB * HID; i += 256) zr[i] = 0.f;
        for (int i = tid; i < NFLAGS; i += 256)
            g_flag[i] = (i == 0 || i == ZROW) ? 4u : 0u;
    }
}

// ---------------- c_pre = W1b @ ne + b1 ----------------
__global__ __launch_bounds__(256) void cpre_kernel(const float* __restrict__ emb_table,
                                                   const float* __restrict__ b1) {
    __shared__ float sne[32][64];
    __shared__ float sw[64][128];
    int tid = threadIdx.x;
    int row0 = blockIdx.x * 32;
    for (int i = tid; i < 32 * 64; i += 256) {
        int r = i >> 6, e = i & 63;
        sne[r][e] = emb_table[(size_t)(2 + row0 + r) * 64 + e];
    }
    for (int i = tid; i < 64 * 128; i += 256)
        sw[i >> 7][i & 127] = g_W1bT[i];
    __syncthreads();
    int c = tid & 127;
    int rh = (tid >> 7) * 16;
    float acc[16];
    float bv = b1[c];
#pragma unroll
    for (int rr = 0; rr < 16; rr++) acc[rr] = bv;
    for (int k = 0; k < 64; k++) {
        float w = sw[k][c];
#pragma unroll
        for (int rr = 0; rr < 16; rr++) acc[rr] += sne[rh + rr][k] * w;
    }
#pragma unroll
    for (int rr = 0; rr < 16; rr++)
        g_cpre[(size_t)(row0 + rh + rr) * HID + c] = acc[rr];
}

// ---------------- persistent DAG kernel: 4 autonomous warpgroups ----------------
__global__ __launch_bounds__(NTHREADS, 1)
void dag_kernel(float* __restrict__ out, const int* __restrict__ pidx,
                const float* __restrict__ b2) {
    extern __shared__ char smc[];
    const uint32_t sb = smem_u32(smc);
    const int tid = threadIdx.x;
    const int wid = tid >> 5, lane = tid & 31;
    const int n0 = blockIdx.x * 4;

    const int nn = wid >> 2;            // warpgroup = node index within CTA
    const int cw = wid & 3;             // warp-in-group = column group
    const int node = n0 + nn;
    const int r0 = nn * 32;             // this node's tile rows
    const int c0 = cw * 32;             // this warp's output columns
    const int bbase = cw * 8;           // gather batch base
    const int barid = 1 + nn;           // named barrier id (1..4)
    const int tq = lane >> 2;
    const int tc = (lane & 3) * 2;

    // one-time: stationary W1/W2 tiles + b2
    {
        const uint2* w1h = (const uint2*)g_w1hi;
        const uint2* w1l = (const uint2*)g_w1lo;
        const uint2* w2h = (const uint2*)g_w2hi;
        const uint2* w2l = (const uint2*)g_w2lo;
        for (int i = tid; i < 128 * 32; i += NTHREADS) {
            int r = i >> 5, q = i & 31;
            uint32_t off = (uint32_t)r * STRB + q * 8;
            *(uint2*)(smc + SM_W1HI + off) = w1h[i];
            *(uint2*)(smc + SM_W1LO + off) = w1l[i];
            *(uint2*)(smc + SM_W2HI + off) = w2h[i];
            *(uint2*)(smc + SM_W2LO + off) = w2l[i];
        }
        if (tid < 128) ((float*)(smc + SM_B2))[tid] = b2[tid];
    }
    __syncthreads();
    const float* s_b2 = (const float*)(smc + SM_B2);

    for (int d = 0; d < DEPTH; d++) {
        const int orow = 1 + d * NODES + node;   // out row == g_buf row

        // ---- gather: direct pidx load, poll parent flags, sum, pv->out, split->A ----
        {
            int prow = -1;
            if (lane < NPAR) {
                int s = __ldg(&pidx[(d * NODES + node) * NPAR + lane]);
                prow = s ? (s - 1) : -1;
                if (prow >= 0) {
                    volatile unsigned* f = &g_flag[prow];
                    while (*f < 4u) __nanosleep(32);
                }
            }
            __syncwarp();
            __threadfence();   // acquire: parent rows visible
            float vx[8], vy[8], vz[8], vw[8];
#pragma unroll
            for (int rr = 0; rr < 8; rr++) { vx[rr] = 0.f; vy[rr] = 0.f; vz[rr] = 0.f; vw[rr] = 0.f; }
#pragma unroll
            for (int p = 0; p < NPAR; p++) {
                int row = __shfl_sync(0xFFFFFFFFu, prow, p);
                if (row < 0) continue;          // warp-uniform skip
                const float* pb = g_buf + (size_t)row * (NB * HID)
                                + (size_t)bbase * HID + lane * 4;
#pragma unroll
                for (int rr = 0; rr < 8; rr++) {
                    float4 v = *(const float4*)(pb + (size_t)rr * HID);
                    vx[rr] += v.x; vy[rr] += v.y; vz[rr] += v.z; vw[rr] += v.w;
                }
            }
#pragma unroll
            for (int rr = 0; rr < 8; rr++) {
                int b = bbase + rr;
                // pv -> out row (fp32 exact; read back at epilogue)
                *(float4*)(out + ((size_t)b * ROWS_PER_B + orow) * HID + lane * 4) =
                    make_float4(vx[rr], vy[rr], vz[rr], vw[rr]);
                int r = r0 + b;
                uint32_t h0, l0, h1, l1;
                split2(vx[rr], vy[rr], h0, l0);
                split2(vz[rr], vw[rr], h1, l1);
                uint32_t o = (uint32_t)r * STRB + lane * 8;
                *(uint32_t*)(smc + SM_AHI + o) = h0;
                *(uint32_t*)(smc + SM_AHI + o + 4) = h1;
                *(uint32_t*)(smc + SM_ALO + o) = l0;
                *(uint32_t*)(smc + SM_ALO + o + 4) = l1;
            }
        }
        named_bar(barid);      // A tile + pv-out visible within group

        float acc[2][4][4];
#pragma unroll
        for (int mt = 0; mt < 2; mt++)
#pragma unroll
            for (int nt = 0; nt < 4; nt++)
#pragma unroll
                for (int q = 0; q < 4; q++) acc[mt][nt][q] = 0.f;

        // ---- GEMM1: A x W1 ----
        gemm3(sb + SM_AHI, sb + SM_ALO, sb + SM_W1HI, sb + SM_W1LO, r0, c0, lane, acc);
        named_bar(barid);      // group done reading A before H overwrites it

        // ---- relu(D1 + cpre) -> split -> H (A region) ----
        {
            const float* cp = g_cpre + (size_t)(d * NODES + node) * HID;
#pragma unroll
            for (int mt = 0; mt < 2; mt++) {
#pragma unroll
                for (int nt = 0; nt < 4; nt++) {
                    int c = c0 + nt * 8 + tc;
                    float2 cpv = *(const float2*)(cp + c);
                    float v0 = fmaxf(acc[mt][nt][0] + cpv.x, 0.f);
                    float v1 = fmaxf(acc[mt][nt][1] + cpv.y, 0.f);
                    float v2 = fmaxf(acc[mt][nt][2] + cpv.x, 0.f);
                    float v3 = fmaxf(acc[mt][nt][3] + cpv.y, 0.f);
                    uint32_t hi, lo;
                    uint32_t oA = (uint32_t)(r0 + mt * 16 + tq) * STRB + c * 2;
                    uint32_t oB = oA + 8 * STRB;
                    split2(v0, v1, hi, lo);
                    *(uint32_t*)(smc + SM_AHI + oA) = hi;
                    *(uint32_t*)(smc + SM_ALO + oA) = lo;
                    split2(v2, v3, hi, lo);
                    *(uint32_t*)(smc + SM_AHI + oB) = hi;
                    *(uint32_t*)(smc + SM_ALO + oB) = lo;
                }
            }
        }
        named_bar(barid);      // H visible within group

#pragma unroll
        for (int mt = 0; mt < 2; mt++)
#pragma unroll
            for (int nt = 0; nt < 4; nt++)
#pragma unroll
                for (int q = 0; q < 4; q++) acc[mt][nt][q] = 0.f;

        // ---- GEMM2: H x W2 ----
        gemm3(sb + SM_AHI, sb + SM_ALO, sb + SM_W2HI, sb + SM_W2LO, r0, c0, lane, acc);

        // ---- epilogue: out = pv(out row) + D2 + b2 ; mirror to g_buf ----
#pragma unroll
        for (int mt = 0; mt < 2; mt++) {
#pragma unroll
            for (int half = 0; half < 2; half++) {
                int b = mt * 16 + tq + half * 8;
                float* po = out + ((size_t)b * ROWS_PER_B + orow) * HID;
                float* pg = g_buf + ((size_t)orow * NB + b) * HID;
#pragma unroll
                for (int nt = 0; nt < 4; nt++) {
                    int c = c0 + nt * 8 + tc;
                    float2 pv = *(const float2*)(po + c);
                    float2 o;
                    o.x = acc[mt][nt][half * 2 + 0] + s_b2[c] + pv.x;
                    o.y = acc[mt][nt][half * 2 + 1] + s_b2[c + 1] + pv.y;
                    *(float2*)(po + c) = o;
                    *(float2*)(pg + c) = o;
                }
            }
        }

        if (d + 1 == DEPTH) break;
        // ---- publish this warp's quarter of the node ----
        __syncwarp();
        __threadfence();       // release this warp's g_buf stores
        if (lane == 0) atomicAdd(&g_flag[orow], 1u);
        named_bar(barid);      // group GEMM2/epilogue reads done; A/H reusable
    }
}

extern "C" void kernel_launch(void* const* d_in, const int* in_sizes, int n_in,
                              void* d_out, int out_size) {
    const float* embedding  = (const float*)d_in[0];
    const float* emb_table  = (const float*)d_in[1];
    const float* W1         = (const float*)d_in[2];
    const float* b1         = (const float*)d_in[3];
    const float* W2         = (const float*)d_in[4];
    const float* b2         = (const float*)d_in[5];
    const int*   parent_idx = (const int*)d_in[6];
    float* out = (float*)d_out;
    (void)in_sizes; (void)n_in; (void)out_size;

    cudaFuncSetAttribute(dag_kernel,
                         cudaFuncAttributeMaxDynamicSharedMemorySize, SMEM_TOTAL);

    prep_kernel<<<128, 256>>>(embedding, W1, W2, out);
    cpre_kernel<<<DEPTH * NODES / 32, 256>>>(emb_table, b1);
    dag_kernel<<<128, NTHREADS, SMEM_TOTAL>>>(out, parent_idx, b2);
}

// round 13
// speedup vs baseline: 1.3461x; 1.2024x over previous
#include <cuda_runtime.h>
#include <cuda_bf16.h>
#include <cstdint>

#define DEPTH 32
#define NODES 512
#define NPAR 8
#define NB 32
#define HID 128
#define ROWS_PER_B 16385
#define STRB 272            // smem tile row stride bytes (136 bf16)
#define NTHREADS 512
#define ZROW 16385
#define NFLAGS 16386

// ---------------- device statics ----------------
__device__ float g_cpre[DEPTH * NODES * HID];
__device__ float g_W1bT[64 * HID];
__device__ __nv_bfloat16 g_w1hi[HID * HID], g_w1lo[HID * HID];  // [n][k]
__device__ __nv_bfloat16 g_w2hi[HID * HID], g_w2lo[HID * HID];  // [n][k]
__device__ float g_buf[(size_t)(2 + DEPTH * NODES) * NB * HID];
// per-row ready flags: 4 = ready (4 writer-warp arrivals)
__device__ unsigned g_flag[NFLAGS];

// ---------------- helpers ----------------
__device__ __forceinline__ uint32_t smem_u32(const void* p) {
    uint32_t a;
    asm("{ .reg .u64 t; cvta.to.shared.u64 t, %1; cvt.u32.u64 %0, t; }" : "=r"(a) : "l"(p));
    return a;
}
__device__ __forceinline__ void ldsm4(uint32_t addr, uint32_t r[4]) {
    asm volatile("ldmatrix.sync.aligned.m8n8.x4.shared.b16 {%0,%1,%2,%3}, [%4];"
        : "=r"(r[0]), "=r"(r[1]), "=r"(r[2]), "=r"(r[3]) : "r"(addr));
}
__device__ __forceinline__ void mma16816(float c[4], const uint32_t a[4],
                                         uint32_t b0, uint32_t b1) {
    asm volatile("mma.sync.aligned.m16n8k16.row.col.f32.bf16.bf16.f32 "
        "{%0,%1,%2,%3}, {%4,%5,%6,%7}, {%8,%9}, {%0,%1,%2,%3};"
        : "+f"(c[0]), "+f"(c[1]), "+f"(c[2]), "+f"(c[3])
        : "r"(a[0]), "r"(a[1]), "r"(a[2]), "r"(a[3]), "r"(b0), "r"(b1));
}
__device__ __forceinline__ void named_bar(int id) {
    asm volatile("bar.sync %0, 128;" :: "r"(id) : "memory");
}
__device__ __forceinline__ void split2(float a, float b, uint32_t& hi, uint32_t& lo) {
    __nv_bfloat16 ah = __float2bfloat16(a), bh = __float2bfloat16(b);
    __nv_bfloat16 al = __float2bfloat16(a - __bfloat162float(ah));
    __nv_bfloat16 bl = __float2bfloat16(b - __bfloat162float(bh));
    hi = (uint32_t)__bfloat16_as_ushort(ah) | ((uint32_t)__bfloat16_as_ushort(bh) << 16);
    lo = (uint32_t)__bfloat16_as_ushort(al) | ((uint32_t)__bfloat16_as_ushort(bl) << 16);
}
__device__ __forceinline__ float2 unsplit2(uint32_t h, uint32_t l) {
    float ax = __bfloat162float(__ushort_as_bfloat16((unsigned short)(h & 0xFFFF)));
    float ay = __bfloat162float(__ushort_as_bfloat16((unsigned short)(h >> 16)));
    float bx = __bfloat162float(__ushort_as_bfloat16((unsigned short)(l & 0xFFFF)));
    float by = __bfloat162float(__ushort_as_bfloat16((unsigned short)(l >> 16)));
    return make_float2(ax + bx, ay + by);
}

// ---------------- smem layout ----------------
#define TILE_B  (128 * STRB)              // 34816
#define SM_W1HI 0
#define SM_W1LO (1 * TILE_B)
#define SM_W2HI (2 * TILE_B)
#define SM_W2LO (3 * TILE_B)
#define SM_AHI  (4 * TILE_B)              // A tile (pv split), then H tile
#define SM_ALO  (5 * TILE_B)
#define SM_B2   (6 * TILE_B)              // 512 B
#define SMEM_TOTAL (6 * TILE_B + 512)

// fused 3-term split GEMM for a 32x32 warp tile:
// acc += Ahi*Bhi + Alo*Bhi + Ahi*Blo  (K=128)
__device__ __forceinline__ void gemm3(uint32_t AhiB, uint32_t AloB,
                                      uint32_t BhiB, uint32_t BloB,
                                      int r0, int c0, int lane,
                                      float acc[2][4][4]) {
    const uint32_t rsel = (uint32_t)(lane & 15);
    const uint32_t ksel = (uint32_t)(lane >> 4) * 16;
    const uint32_t aoff = (r0 + rsel) * STRB + ksel;
    const uint32_t boff = (c0 + rsel) * STRB + ksel;
    uint32_t ah0 = AhiB + aoff, ah1 = ah0 + 16 * STRB;
    uint32_t al0 = AloB + aoff, al1 = al0 + 16 * STRB;
    uint32_t bh0 = BhiB + boff, bh1 = bh0 + 16 * STRB;
    uint32_t bl0 = BloB + boff, bl1 = bl0 + 16 * STRB;
#pragma unroll
    for (int kc = 0; kc < 8; kc++) {
        const uint32_t kb = kc * 32;
        uint32_t Ah0[4], Ah1[4], Al0[4], Al1[4];
        uint32_t Bh0[4], Bh1[4], Bl0[4], Bl1[4];
        ldsm4(ah0 + kb, Ah0); ldsm4(ah1 + kb, Ah1);
        ldsm4(bh0 + kb, Bh0); ldsm4(bh1 + kb, Bh1);
        ldsm4(al0 + kb, Al0); ldsm4(al1 + kb, Al1);
        ldsm4(bl0 + kb, Bl0); ldsm4(bl1 + kb, Bl1);
        mma16816(acc[0][0], Ah0, Bh0[0], Bh0[2]);
        mma16816(acc[0][1], Ah0, Bh0[1], Bh0[3]);
        mma16816(acc[0][2], Ah0, Bh1[0], Bh1[2]);
        mma16816(acc[0][3], Ah0, Bh1[1], Bh1[3]);
        mma16816(acc[1][0], Ah1, Bh0[0], Bh0[2]);
        mma16816(acc[1][1], Ah1, Bh0[1], Bh0[3]);
        mma16816(acc[1][2], Ah1, Bh1[0], Bh1[2]);
        mma16816(acc[1][3], Ah1, Bh1[1], Bh1[3]);
        mma16816(acc[0][0], Al0, Bh0[0], Bh0[2]);
        mma16816(acc[0][1], Al0, Bh0[1], Bh0[3]);
        mma16816(acc[0][2], Al0, Bh1[0], Bh1[2]);
        mma16816(acc[0][3], Al0, Bh1[1], Bh1[3]);
        mma16816(acc[1][0], Al1, Bh0[0], Bh0[2]);
        mma16816(acc[1][1], Al1, Bh0[1], Bh0[3]);
        mma16816(acc[1][2], Al1, Bh1[0], Bh1[2]);
        mma16816(acc[1][3], Al1, Bh1[1], Bh1[3]);
        mma16816(acc[0][0], Ah0, Bl0[0], Bl0[2]);
        mma16816(acc[0][1], Ah0, Bl0[1], Bl0[3]);
        mma16816(acc[0][2], Ah0, Bl1[0], Bl1[2]);
        mma16816(acc[0][3], Ah0, Bl1[1], Bl1[3]);
        mma16816(acc[1][0], Ah1, Bl0[0], Bl0[2]);
        mma16816(acc[1][1], Ah1, Bl0[1], Bl0[3]);
        mma16816(acc[1][2], Ah1, Bl1[0], Bl1[2]);
        mma16816(acc[1][3], Ah1, Bl1[1], Bl1[3]);
    }
}

// ---------------- prep ----------------
__global__ void prep_kernel(const float* __restrict__ emb,
                            const float* __restrict__ W1,
                            const float* __restrict__ W2,
                            float* __restrict__ out) {
    int n = blockIdx.x, tid = threadIdx.x;  // 128 x 256
    for (int k = tid; k < 192; k += 256) {
        float v = W1[n * 192 + k];
        if (k < 128) {
            __nv_bfloat16 h = __float2bfloat16(v);
            g_w1hi[n * HID + k] = h;
            g_w1lo[n * HID + k] = __float2bfloat16(v - __bfloat162float(h));
        } else {
            g_W1bT[(k - 128) * HID + n] = v;
        }
    }
    for (int k = tid; k < 128; k += 256) {
        float v = W2[n * HID + k];
        __nv_bfloat16 h = __float2bfloat16(v);
        g_w2hi[n * HID + k] = h;
        g_w2lo[n * HID + k] = __float2bfloat16(v - __bfloat162float(h));
    }
    int g = n * 256 + tid;
    if (g < NB * HID) {
        int b = g >> 7, c = g & 127;
        out[(size_t)b * ROWS_PER_B * HID + c] = emb[g];
        g_buf[(size_t)b * HID + c] = emb[g];      // g_row 0 = root
    }
    if (n == 0) {
        float* zr = g_buf + (size_t)ZROW * NB * HID;
        for (int i = tid; i < NB * HID; i += 256) zr[i] = 0.f;
        for (int i = tid; i < NFLAGS; i += 256)
            g_flag[i] = (i == 0 || i == ZROW) ? 4u : 0u;
    }
}

// ---------------- c_pre = W1b @ ne + b1 ----------------
__global__ __launch_bounds__(256) void cpre_kernel(const float* __restrict__ emb_table,
                                                   const float* __restrict__ b1) {
    __shared__ float sne[32][64];
    __shared__ float sw[64][128];
    int tid = threadIdx.x;
    int row0 = blockIdx.x * 32;
    for (int i = tid; i < 32 * 64; i += 256) {
        int r = i >> 6, e = i & 63;
        sne[r][e] = emb_table[(size_t)(2 + row0 + r) * 64 + e];
    }
    for (int i = tid; i < 64 * 128; i += 256)
        sw[i >> 7][i & 127] = g_W1bT[i];
    __syncthreads();
    int c = tid & 127;
    int rh = (tid >> 7) * 16;
    float acc[16];
    float bv = b1[c];
#pragma unroll
    for (int rr = 0; rr < 16; rr++) acc[rr] = bv;
    for (int k = 0; k < 64; k++) {
        float w = sw[k][c];
#pragma unroll
        for (int rr = 0; rr < 16; rr++) acc[rr] += sne[rh + rr][k] * w;
    }
#pragma unroll
    for (int rr = 0; rr < 16; rr++)
        g_cpre[(size_t)(row0 + rh + rr) * HID + c] = acc[rr];
}

// ---------------- persistent DAG kernel: 4 autonomous warpgroups ----------------
__global__ __launch_bounds__(NTHREADS, 1)
void dag_kernel(float* __restrict__ out, const int* __restrict__ pidx,
                const float* __restrict__ b2) {
    extern __shared__ char smc[];
    const uint32_t sb = smem_u32(smc);
    const int tid = threadIdx.x;
    const int wid = tid >> 5, lane = tid & 31;
    const int n0 = blockIdx.x * 4;

    const int nn = wid >> 2;            // warpgroup = node index within CTA
    const int cw = wid & 3;             // warp-in-group = column group
    const int node = n0 + nn;
    const int r0 = nn * 32;             // this node's tile rows
    const int c0 = cw * 32;             // this warp's output columns
    const int bbase = cw * 8;           // gather batch base
    const int barid = 1 + nn;           // named barrier id (1..4)
    const int tq = lane >> 2;
    const int tc = (lane & 3) * 2;

    // one-time: stationary W1/W2 tiles + b2
    {
        const uint2* w1h = (const uint2*)g_w1hi;
        const uint2* w1l = (const uint2*)g_w1lo;
        const uint2* w2h = (const uint2*)g_w2hi;
        const uint2* w2l = (const uint2*)g_w2lo;
        for (int i = tid; i < 128 * 32; i += NTHREADS) {
            int r = i >> 5, q = i & 31;
            uint32_t off = (uint32_t)r * STRB + q * 8;
            *(uint2*)(smc + SM_W1HI + off) = w1h[i];
            *(uint2*)(smc + SM_W1LO + off) = w1l[i];
            *(uint2*)(smc + SM_W2HI + off) = w2h[i];
            *(uint2*)(smc + SM_W2LO + off) = w2l[i];
        }
        if (tid < 128) ((float*)(smc + SM_B2))[tid] = b2[tid];
    }
    __syncthreads();
    const float* s_b2 = (const float*)(smc + SM_B2);

    for (int d = 0; d < DEPTH; d++) {
        const int orow = 1 + d * NODES + node;   // out row == g_buf row

        // ---- gather: pidx load, poll parent flags, sum, split -> A tiles ----
        {
            int prow = -1;
            if (lane < NPAR) {
                int s = __ldg(&pidx[(d * NODES + node) * NPAR + lane]);
                prow = s ? (s - 1) : -1;
                if (prow >= 0) {
                    volatile unsigned* f = &g_flag[prow];
                    while (*f < 4u) __nanosleep(32);
                }
            }
            __syncwarp();
            __threadfence();   // acquire: parent rows visible
            float vx[8], vy[8], vz[8], vw[8];
#pragma unroll
            for (int rr = 0; rr < 8; rr++) { vx[rr] = 0.f; vy[rr] = 0.f; vz[rr] = 0.f; vw[rr] = 0.f; }
#pragma unroll
            for (int p = 0; p < NPAR; p++) {
                int row = __shfl_sync(0xFFFFFFFFu, prow, p);
                if (row < 0) continue;          // warp-uniform skip
                const float* pb = g_buf + (size_t)row * (NB * HID)
                                + (size_t)bbase * HID + lane * 4;
#pragma unroll
                for (int rr = 0; rr < 8; rr++) {
                    float4 v = *(const float4*)(pb + (size_t)rr * HID);
                    vx[rr] += v.x; vy[rr] += v.y; vz[rr] += v.z; vw[rr] += v.w;
                }
            }
#pragma unroll
            for (int rr = 0; rr < 8; rr++) {
                int r = r0 + bbase + rr;
                uint32_t h0, l0, h1, l1;
                split2(vx[rr], vy[rr], h0, l0);
                split2(vz[rr], vw[rr], h1, l1);
                uint32_t o = (uint32_t)r * STRB + lane * 8;
                *(uint32_t*)(smc + SM_AHI + o) = h0;
                *(uint32_t*)(smc + SM_AHI + o + 4) = h1;
                *(uint32_t*)(smc + SM_ALO + o) = l0;
                *(uint32_t*)(smc + SM_ALO + o + 4) = l1;
            }
        }
        named_bar(barid);      // A tile (pv split) visible within group

        float acc[2][4][4];
#pragma unroll
        for (int mt = 0; mt < 2; mt++)
#pragma unroll
            for (int nt = 0; nt < 4; nt++)
#pragma unroll
                for (int q = 0; q < 4; q++) acc[mt][nt][q] = 0.f;

        // ---- GEMM1: A x W1 ----
        gemm3(sb + SM_AHI, sb + SM_ALO, sb + SM_W1HI, sb + SM_W1LO, r0, c0, lane, acc);
        named_bar(barid);      // group done reading A for GEMM1

        // ---- seed GEMM2 accumulator with pv read from A tiles (MMA layout) ----
        float acc2[2][4][4];
#pragma unroll
        for (int mt = 0; mt < 2; mt++) {
#pragma unroll
            for (int half = 0; half < 2; half++) {
                int b = mt * 16 + tq + half * 8;
                int rA = r0 + b;
#pragma unroll
                for (int nt = 0; nt < 4; nt++) {
                    int c = c0 + nt * 8 + tc;
                    uint32_t off = (uint32_t)rA * STRB + c * 2;
                    float2 pvv = unsplit2(*(const uint32_t*)(smc + SM_AHI + off),
                                          *(const uint32_t*)(smc + SM_ALO + off));
                    acc2[mt][nt][half * 2 + 0] = pvv.x;
                    acc2[mt][nt][half * 2 + 1] = pvv.y;
                }
            }
        }
        named_bar(barid);      // pv reads done before relu overwrites A

        // ---- relu(D1 + cpre) -> split -> H (A region) ----
        {
            const float* cp = g_cpre + (size_t)(d * NODES + node) * HID;
#pragma unroll
            for (int mt = 0; mt < 2; mt++) {
#pragma unroll
                for (int nt = 0; nt < 4; nt++) {
                    int c = c0 + nt * 8 + tc;
                    float2 cpv = *(const float2*)(cp + c);
                    float v0 = fmaxf(acc[mt][nt][0] + cpv.x, 0.f);
                    float v1 = fmaxf(acc[mt][nt][1] + cpv.y, 0.f);
                    float v2 = fmaxf(acc[mt][nt][2] + cpv.x, 0.f);
                    float v3 = fmaxf(acc[mt][nt][3] + cpv.y, 0.f);
                    uint32_t hi, lo;
                    uint32_t oA = (uint32_t)(r0 + mt * 16 + tq) * STRB + c * 2;
                    uint32_t oB = oA + 8 * STRB;
                    split2(v0, v1, hi, lo);
                    *(uint32_t*)(smc + SM_AHI + oA) = hi;
                    *(uint32_t*)(smc + SM_ALO + oA) = lo;
                    split2(v2, v3, hi, lo);
                    *(uint32_t*)(smc + SM_AHI + oB) = hi;
                    *(uint32_t*)(smc + SM_ALO + oB) = lo;
                }
            }
        }
        named_bar(barid);      // H visible within group

        // ---- GEMM2: acc2(pv) += H x W2 ----
        gemm3(sb + SM_AHI, sb + SM_ALO, sb + SM_W2HI, sb + SM_W2LO, r0, c0, lane, acc2);

        // ---- epilogue: out = acc2 + b2 ; mirror to g_buf ----
#pragma unroll
        for (int mt = 0; mt < 2; mt++) {
#pragma unroll
            for (int half = 0; half < 2; half++) {
                int b = mt * 16 + tq + half * 8;
                float* po = out + ((size_t)b * ROWS_PER_B + orow) * HID;
                float* pg = g_buf + ((size_t)orow * NB + b) * HID;
#pragma unroll
                for (int nt = 0; nt < 4; nt++) {
                    int c = c0 + nt * 8 + tc;
                    float2 o;
                    o.x = acc2[mt][nt][half * 2 + 0] + s_b2[c];
                    o.y = acc2[mt][nt][half * 2 + 1] + s_b2[c + 1];
                    *(float2*)(po + c) = o;
                    if (d + 1 < DEPTH) *(float2*)(pg + c) = o;
                }
            }
        }

        if (d + 1 == DEPTH) break;
        // ---- publish this warp's quarter of the node ----
        __syncwarp();
        __threadfence();       // release this warp's g_buf stores
        if (lane == 0) atomicAdd(&g_flag[orow], 1u);
        named_bar(barid);      // group GEMM2 reads done; A/H reusable
    }
}

extern "C" void kernel_launch(void* const* d_in, const int* in_sizes, int n_in,
                              void* d_out, int out_size) {
    const float* embedding  = (const float*)d_in[0];
    const float* emb_table  = (const float*)d_in[1];
    const float* W1         = (const float*)d_in[2];
    const float* b1         = (const float*)d_in[3];
    const float* W2         = (const float*)d_in[4];
    const float* b2         = (const float*)d_in[5];
    const int*   parent_idx = (const int*)d_in[6];
    float* out = (float*)d_out;
    (void)in_sizes; (void)n_in; (void)out_size;

    cudaFuncSetAttribute(dag_kernel,
                         cudaFuncAttributeMaxDynamicSharedMemorySize, SMEM_TOTAL);

    prep_kernel<<<128, 256>>>(embedding, W1, W2, out);
    cpre_kernel<<<DEPTH * NODES / 32, 256>>>(emb_table, b1);
    dag_kernel<<<128, NTHREADS, SMEM_TOTAL>>>(out, parent_idx, b2);
}

// round 14
// speedup vs baseline: 1.3781x; 1.0238x over previous
#include <cuda_runtime.h>
#include <cuda_bf16.h>
#include <cstdint>

#define DEPTH 32
#define NODES 512
#define NPAR 8
#define NB 32
#define HID 128
#define ROWS_PER_B 16385
#define STRB 272            // smem tile row stride bytes (136 bf16)
#define NTHREADS 512
#define ZROW 16385
#define NFLAGS 16386

// ---------------- device statics ----------------
__device__ float g_cpre[DEPTH * NODES * HID];
__device__ float g_W1bT[64 * HID];
__device__ __nv_bfloat16 g_w1hi[HID * HID], g_w1lo[HID * HID];  // [n][k]
__device__ __nv_bfloat16 g_w2hi[HID * HID], g_w2lo[HID * HID];  // [n][k]
__device__ float g_buf[(size_t)(2 + DEPTH * NODES) * NB * HID];
// per-row ready flags: 4 = ready (4 writer-warp arrivals)
__device__ unsigned g_flag[NFLAGS];

// ---------------- helpers ----------------
__device__ __forceinline__ uint32_t smem_u32(const void* p) {
    uint32_t a;
    asm("{ .reg .u64 t; cvta.to.shared.u64 t, %1; cvt.u32.u64 %0, t; }" : "=r"(a) : "l"(p));
    return a;
}
__device__ __forceinline__ void ldsm4(uint32_t addr, uint32_t r[4]) {
    asm volatile("ldmatrix.sync.aligned.m8n8.x4.shared.b16 {%0,%1,%2,%3}, [%4];"
        : "=r"(r[0]), "=r"(r[1]), "=r"(r[2]), "=r"(r[3]) : "r"(addr));
}
__device__ __forceinline__ void mma16816(float c[4], const uint32_t a[4],
                                         uint32_t b0, uint32_t b1) {
    asm volatile("mma.sync.aligned.m16n8k16.row.col.f32.bf16.bf16.f32 "
        "{%0,%1,%2,%3}, {%4,%5,%6,%7}, {%8,%9}, {%0,%1,%2,%3};"
        : "+f"(c[0]), "+f"(c[1]), "+f"(c[2]), "+f"(c[3])
        : "r"(a[0]), "r"(a[1]), "r"(a[2]), "r"(a[3]), "r"(b0), "r"(b1));
}
__device__ __forceinline__ void named_bar(int id) {
    asm volatile("bar.sync %0, 128;" :: "r"(id) : "memory");
}
__device__ __forceinline__ void split2(float a, float b, uint32_t& hi, uint32_t& lo) {
    __nv_bfloat16 ah = __float2bfloat16(a), bh = __float2bfloat16(b);
    __nv_bfloat16 al = __float2bfloat16(a - __bfloat162float(ah));
    __nv_bfloat16 bl = __float2bfloat16(b - __bfloat162float(bh));
    hi = (uint32_t)__bfloat16_as_ushort(ah) | ((uint32_t)__bfloat16_as_ushort(bh) << 16);
    lo = (uint32_t)__bfloat16_as_ushort(al) | ((uint32_t)__bfloat16_as_ushort(bl) << 16);
}
__device__ __forceinline__ float2 unsplit2(uint32_t h, uint32_t l) {
    float ax = __bfloat162float(__ushort_as_bfloat16((unsigned short)(h & 0xFFFF)));
    float ay = __bfloat162float(__ushort_as_bfloat16((unsigned short)(h >> 16)));
    float bx = __bfloat162float(__ushort_as_bfloat16((unsigned short)(l & 0xFFFF)));
    float by = __bfloat162float(__ushort_as_bfloat16((unsigned short)(l >> 16)));
    return make_float2(ax + bx, ay + by);
}

// ---------------- smem layout ----------------
#define TILE_B  (128 * STRB)              // 34816
#define SM_W1HI 0
#define SM_W1LO (1 * TILE_B)
#define SM_W2HI (2 * TILE_B)
#define SM_W2LO (3 * TILE_B)
#define SM_AHI  (4 * TILE_B)              // A tile (pv split), then H tile
#define SM_ALO  (5 * TILE_B)
#define SM_B2   (6 * TILE_B)              // 512 B
#define SMEM_TOTAL (6 * TILE_B + 512)

// fused 3-term split GEMM for a 32x32 warp tile:
// acc += Ahi*Bhi + Alo*Bhi + Ahi*Blo  (K=128)
__device__ __forceinline__ void gemm3(uint32_t AhiB, uint32_t AloB,
                                      uint32_t BhiB, uint32_t BloB,
                                      int r0, int c0, int lane,
                                      float acc[2][4][4]) {
    const uint32_t rsel = (uint32_t)(lane & 15);
    const uint32_t ksel = (uint32_t)(lane >> 4) * 16;
    const uint32_t aoff = (r0 + rsel) * STRB + ksel;
    const uint32_t boff = (c0 + rsel) * STRB + ksel;
    uint32_t ah0 = AhiB + aoff, ah1 = ah0 + 16 * STRB;
    uint32_t al0 = AloB + aoff, al1 = al0 + 16 * STRB;
    uint32_t bh0 = BhiB + boff, bh1 = bh0 + 16 * STRB;
    uint32_t bl0 = BloB + boff, bl1 = bl0 + 16 * STRB;
#pragma unroll
    for (int kc = 0; kc < 8; kc++) {
        const uint32_t kb = kc * 32;
        uint32_t Ah0[4], Ah1[4], Al0[4], Al1[4];
        uint32_t Bh0[4], Bh1[4], Bl0[4], Bl1[4];
        ldsm4(ah0 + kb, Ah0); ldsm4(ah1 + kb, Ah1);
        ldsm4(bh0 + kb, Bh0); ldsm4(bh1 + kb, Bh1);
        ldsm4(al0 + kb, Al0); ldsm4(al1 + kb, Al1);
        ldsm4(bl0 + kb, Bl0); ldsm4(bl1 + kb, Bl1);
        mma16816(acc[0][0], Ah0, Bh0[0], Bh0[2]);
        mma16816(acc[0][1], Ah0, Bh0[1], Bh0[3]);
        mma16816(acc[0][2], Ah0, Bh1[0], Bh1[2]);
        mma16816(acc[0][3], Ah0, Bh1[1], Bh1[3]);
        mma16816(acc[1][0], Ah1, Bh0[0], Bh0[2]);
        mma16816(acc[1][1], Ah1, Bh0[1], Bh0[3]);
        mma16816(acc[1][2], Ah1, Bh1[0], Bh1[2]);
        mma16816(acc[1][3], Ah1, Bh1[1], Bh1[3]);
        mma16816(acc[0][0], Al0, Bh0[0], Bh0[2]);
        mma16816(acc[0][1], Al0, Bh0[1], Bh0[3]);
        mma16816(acc[0][2], Al0, Bh1[0], Bh1[2]);
        mma16816(acc[0][3], Al0, Bh1[1], Bh1[3]);
        mma16816(acc[1][0], Al1, Bh0[0], Bh0[2]);
        mma16816(acc[1][1], Al1, Bh0[1], Bh0[3]);
        mma16816(acc[1][2], Al1, Bh1[0], Bh1[2]);
        mma16816(acc[1][3], Al1, Bh1[1], Bh1[3]);
        mma16816(acc[0][0], Ah0, Bl0[0], Bl0[2]);
        mma16816(acc[0][1], Ah0, Bl0[1], Bl0[3]);
        mma16816(acc[0][2], Ah0, Bl1[0], Bl1[2]);
        mma16816(acc[0][3], Ah0, Bl1[1], Bl1[3]);
        mma16816(acc[1][0], Ah1, Bl0[0], Bl0[2]);
        mma16816(acc[1][1], Ah1, Bl0[1], Bl0[3]);
        mma16816(acc[1][2], Ah1, Bl1[0], Bl1[2]);
        mma16816(acc[1][3], Ah1, Bl1[1], Bl1[3]);
    }
}

// ---------------- prep ----------------
__global__ void prep_kernel(const float* __restrict__ emb,
                            const float* __restrict__ W1,
                            const float* __restrict__ W2,
                            float* __restrict__ out) {
    int n = blockIdx.x, tid = threadIdx.x;  // 128 x 256
    for (int k = tid; k < 192; k += 256) {
        float v = W1[n * 192 + k];
        if (k < 128) {
            __nv_bfloat16 h = __float2bfloat16(v);
            g_w1hi[n * HID + k] = h;
            g_w1lo[n * HID + k] = __float2bfloat16(v - __bfloat162float(h));
        } else {
            g_W1bT[(k - 128) * HID + n] = v;
        }
    }
    for (int k = tid; k < 128; k += 256) {
        float v = W2[n * HID + k];
        __nv_bfloat16 h = __float2bfloat16(v);
        g_w2hi[n * HID + k] = h;
        g_w2lo[n * HID + k] = __float2bfloat16(v - __bfloat162float(h));
    }
    int g = n * 256 + tid;
    if (g < NB * HID) {
        int b = g >> 7, c = g & 127;
        out[(size_t)b * ROWS_PER_B * HID + c] = emb[g];
        g_buf[(size_t)b * HID + c] = emb[g];      // g_row 0 = root
    }
    if (n == 0) {
        float* zr = g_buf + (size_t)ZROW * NB * HID;
        for (int i = tid; i < NB * HID; i += 256) zr[i] = 0.f;
        for (int i = tid; i < NFLAGS; i += 256)
            g_flag[i] = (i == 0 || i == ZROW) ? 4u : 0u;
    }
}

// ---------------- c_pre = W1b @ ne + b1 ----------------
__global__ __launch_bounds__(256) void cpre_kernel(const float* __restrict__ emb_table,
                                                   const float* __restrict__ b1) {
    __shared__ float sne[32][64];
    __shared__ float sw[64][128];
    int tid = threadIdx.x;
    int row0 = blockIdx.x * 32;
    for (int i = tid; i < 32 * 64; i += 256) {
        int r = i >> 6, e = i & 63;
        sne[r][e] = emb_table[(size_t)(2 + row0 + r) * 64 + e];
    }
    for (int i = tid; i < 64 * 128; i += 256)
        sw[i >> 7][i & 127] = g_W1bT[i];
    __syncthreads();
    int c = tid & 127;
    int rh = (tid >> 7) * 16;
    float acc[16];
    float bv = b1[c];
#pragma unroll
    for (int rr = 0; rr < 16; rr++) acc[rr] = bv;
    for (int k = 0; k < 64; k++) {
        float w = sw[k][c];
#pragma unroll
        for (int rr = 0; rr < 16; rr++) acc[rr] += sne[rh + rr][k] * w;
    }
#pragma unroll
    for (int rr = 0; rr < 16; rr++)
        g_cpre[(size_t)(row0 + rh + rr) * HID + c] = acc[rr];
}

// ---------------- persistent DAG kernel: 4 autonomous warpgroups ----------------
__global__ __launch_bounds__(NTHREADS, 1)
void dag_kernel(float* __restrict__ out, const int* __restrict__ pidx,
                const float* __restrict__ b2) {
    extern __shared__ char smc[];
    const uint32_t sb = smem_u32(smc);
    const int tid = threadIdx.x;
    const int wid = tid >> 5, lane = tid & 31;
    const int n0 = blockIdx.x * 4;

    const int nn = wid >> 2;            // warpgroup = node index within CTA
    const int cw = wid & 3;             // warp-in-group = column group
    const int node = n0 + nn;
    const int r0 = nn * 32;             // this node's tile rows
    const int c0 = cw * 32;             // this warp's output columns
    const int bbase = cw * 8;           // gather batch base
    const int barid = 1 + nn;           // named barrier id (1..4)
    const int tq = lane >> 2;
    const int tc = (lane & 3) * 2;

    // one-time: stationary W1/W2 tiles + b2
    {
        const uint2* w1h = (const uint2*)g_w1hi;
        const uint2* w1l = (const uint2*)g_w1lo;
        const uint2* w2h = (const uint2*)g_w2hi;
        const uint2* w2l = (const uint2*)g_w2lo;
        for (int i = tid; i < 128 * 32; i += NTHREADS) {
            int r = i >> 5, q = i & 31;
            uint32_t off = (uint32_t)r * STRB + q * 8;
            *(uint2*)(smc + SM_W1HI + off) = w1h[i];
            *(uint2*)(smc + SM_W1LO + off) = w1l[i];
            *(uint2*)(smc + SM_W2HI + off) = w2h[i];
            *(uint2*)(smc + SM_W2LO + off) = w2l[i];
        }
        if (tid < 128) ((float*)(smc + SM_B2))[tid] = b2[tid];
    }
    __syncthreads();
    const float* s_b2 = (const float*)(smc + SM_B2);

    for (int d = 0; d < DEPTH; d++) {
        const int orow = 1 + d * NODES + node;   // out row == g_buf row

        // ---- gather: pidx load, poll parent flags, sum, split -> A tiles ----
        {
            int prow = -1;
            if (lane < NPAR) {
                int s = __ldg(&pidx[(d * NODES + node) * NPAR + lane]);
                prow = s ? (s - 1) : -1;
                if (prow >= 0) {
                    volatile unsigned* f = &g_flag[prow];
                    while (*f < 4u) __nanosleep(32);
                }
            }
            __syncwarp();
            __threadfence();   // acquire: parent rows visible
            float vx[8], vy[8], vz[8], vw[8];
#pragma unroll
            for (int rr = 0; rr < 8; rr++) { vx[rr] = 0.f; vy[rr] = 0.f; vz[rr] = 0.f; vw[rr] = 0.f; }
#pragma unroll
            for (int p = 0; p < NPAR; p++) {
                int row = __shfl_sync(0xFFFFFFFFu, prow, p);
                if (row < 0) continue;          // warp-uniform skip
                const float* pb = g_buf + (size_t)row * (NB * HID)
                                + (size_t)bbase * HID + lane * 4;
#pragma unroll
                for (int rr = 0; rr < 8; rr++) {
                    float4 v = *(const float4*)(pb + (size_t)rr * HID);
                    vx[rr] += v.x; vy[rr] += v.y; vz[rr] += v.z; vw[rr] += v.w;
                }
            }
#pragma unroll
            for (int rr = 0; rr < 8; rr++) {
                int r = r0 + bbase + rr;
                uint32_t h0, l0, h1, l1;
                split2(vx[rr], vy[rr], h0, l0);
                split2(vz[rr], vw[rr], h1, l1);
                uint32_t o = (uint32_t)r * STRB + lane * 8;
                *(uint32_t*)(smc + SM_AHI + o) = h0;
                *(uint32_t*)(smc + SM_AHI + o + 4) = h1;
                *(uint32_t*)(smc + SM_ALO + o) = l0;
                *(uint32_t*)(smc + SM_ALO + o + 4) = l1;
            }
        }
        named_bar(barid);      // bar1: A tile (pv split) visible within group

        float acc[2][4][4];
#pragma unroll
        for (int mt = 0; mt < 2; mt++)
#pragma unroll
            for (int nt = 0; nt < 4; nt++)
#pragma unroll
                for (int q = 0; q < 4; q++) acc[mt][nt][q] = 0.f;

        // ---- GEMM1: A x W1 ----
        gemm3(sb + SM_AHI, sb + SM_ALO, sb + SM_W1HI, sb + SM_W1LO, r0, c0, lane, acc);

        // ---- seed GEMM2 accumulator with pv from A tiles (read-only, no bar) ----
        float acc2[2][4][4];
#pragma unroll
        for (int mt = 0; mt < 2; mt++) {
#pragma unroll
            for (int half = 0; half < 2; half++) {
                int b = mt * 16 + tq + half * 8;
                int rA = r0 + b;
#pragma unroll
                for (int nt = 0; nt < 4; nt++) {
                    int c = c0 + nt * 8 + tc;
                    uint32_t off = (uint32_t)rA * STRB + c * 2;
                    float2 pvv = unsplit2(*(const uint32_t*)(smc + SM_AHI + off),
                                          *(const uint32_t*)(smc + SM_ALO + off));
                    acc2[mt][nt][half * 2 + 0] = pvv.x;
                    acc2[mt][nt][half * 2 + 1] = pvv.y;
                }
            }
        }
        named_bar(barid);      // bar2: all A reads (GEMM1 + seed) done

        // ---- relu(D1 + cpre) -> split -> H (A region) ----
        {
            const float* cp = g_cpre + (size_t)(d * NODES + node) * HID;
#pragma unroll
            for (int mt = 0; mt < 2; mt++) {
#pragma unroll
                for (int nt = 0; nt < 4; nt++) {
                    int c = c0 + nt * 8 + tc;
                    float2 cpv = *(const float2*)(cp + c);
                    float v0 = fmaxf(acc[mt][nt][0] + cpv.x, 0.f);
                    float v1 = fmaxf(acc[mt][nt][1] + cpv.y, 0.f);
                    float v2 = fmaxf(acc[mt][nt][2] + cpv.x, 0.f);
                    float v3 = fmaxf(acc[mt][nt][3] + cpv.y, 0.f);
                    uint32_t hi, lo;
                    uint32_t oA = (uint32_t)(r0 + mt * 16 + tq) * STRB + c * 2;
                    uint32_t oB = oA + 8 * STRB;
                    split2(v0, v1, hi, lo);
                    *(uint32_t*)(smc + SM_AHI + oA) = hi;
                    *(uint32_t*)(smc + SM_ALO + oA) = lo;
                    split2(v2, v3, hi, lo);
                    *(uint32_t*)(smc + SM_AHI + oB) = hi;
                    *(uint32_t*)(smc + SM_ALO + oB) = lo;
                }
            }
        }
        named_bar(barid);      // bar3: H visible within group

        // ---- GEMM2: acc2(pv) += H x W2 ----
        gemm3(sb + SM_AHI, sb + SM_ALO, sb + SM_W2HI, sb + SM_W2LO, r0, c0, lane, acc2);

        if (d + 1 < DEPTH) {
            // ---- g_buf first (the chain), publish, THEN out (off-chain) ----
#pragma unroll
            for (int mt = 0; mt < 2; mt++) {
#pragma unroll
                for (int half = 0; half < 2; half++) {
                    int b = mt * 16 + tq + half * 8;
                    float* pg = g_buf + ((size_t)orow * NB + b) * HID;
#pragma unroll
                    for (int nt = 0; nt < 4; nt++) {
                        int c = c0 + nt * 8 + tc;
                        float2 o;
                        o.x = acc2[mt][nt][half * 2 + 0] + s_b2[c];
                        o.y = acc2[mt][nt][half * 2 + 1] + s_b2[c + 1];
                        *(float2*)(pg + c) = o;
                    }
                }
            }
            __syncwarp();
            __threadfence();       // release this warp's g_buf stores
            if (lane == 0) atomicAdd(&g_flag[orow], 1u);
            // out writes (not consumed by anyone)
#pragma unroll
            for (int mt = 0; mt < 2; mt++) {
#pragma unroll
                for (int half = 0; half < 2; half++) {
                    int b = mt * 16 + tq + half * 8;
                    float* po = out + ((size_t)b * ROWS_PER_B + orow) * HID;
#pragma unroll
                    for (int nt = 0; nt < 4; nt++) {
                        int c = c0 + nt * 8 + tc;
                        float2 o;
                        o.x = acc2[mt][nt][half * 2 + 0] + s_b2[c];
                        o.y = acc2[mt][nt][half * 2 + 1] + s_b2[c + 1];
                        *(float2*)(po + c) = o;
                    }
                }
            }
            named_bar(barid);      // bar4: group GEMM2 reads done; A/H reusable
        } else {
            // last depth: out only
#pragma unroll
            for (int mt = 0; mt < 2; mt++) {
#pragma unroll
                for (int half = 0; half < 2; half++) {
                    int b = mt * 16 + tq + half * 8;
                    float* po = out + ((size_t)b * ROWS_PER_B + orow) * HID;
#pragma unroll
                    for (int nt = 0; nt < 4; nt++) {
                        int c = c0 + nt * 8 + tc;
                        float2 o;
                        o.x = acc2[mt][nt][half * 2 + 0] + s_b2[c];
                        o.y = acc2[mt][nt][half * 2 + 1] + s_b2[c + 1];
                        *(float2*)(po + c) = o;
                    }
                }
            }
        }
    }
}

extern "C" void kernel_launch(void* const* d_in, const int* in_sizes, int n_in,
                              void* d_out, int out_size) {
    const float* embedding  = (const float*)d_in[0];
    const float* emb_table  = (const float*)d_in[1];
    const float* W1         = (const float*)d_in[2];
    const float* b1         = (const float*)d_in[3];
    const float* W2         = (const float*)d_in[4];
    const float* b2         = (const float*)d_in[5];
    const int*   parent_idx = (const int*)d_in[6];
    float* out = (float*)d_out;
    (void)in_sizes; (void)n_in; (void)out_size;

    cudaFuncSetAttribute(dag_kernel,
                         cudaFuncAttributeMaxDynamicSharedMemorySize, SMEM_TOTAL);

    prep_kernel<<<128, 256>>>(embedding, W1, W2, out);
    cpre_kernel<<<DEPTH * NODES / 32, 256>>>(emb_table, b1);
    dag_kernel<<<128, NTHREADS, SMEM_TOTAL>>>(out, parent_idx, b2);
}

// round 15
// speedup vs baseline: 1.3999x; 1.0158x over previous
#include <cuda_runtime.h>
#include <cuda_bf16.h>
#include <cstdint>

#define DEPTH 32
#define NODES 512
#define NPAR 8
#define NB 32
#define HID 128
#define ROWS_PER_B 16385
#define STRB 272            // smem tile row stride bytes (136 bf16)
#define NTHREADS 512
#define ZROW 16385
#define NFLAGS 16386

// ---------------- device statics ----------------
__device__ float g_cpre[DEPTH * NODES * HID];
__device__ float g_W1bT[64 * HID];
__device__ __nv_bfloat16 g_w1hi[HID * HID], g_w1lo[HID * HID];  // [n][k]
__device__ __nv_bfloat16 g_w2hi[HID * HID], g_w2lo[HID * HID];  // [n][k]
__device__ float g_buf[(size_t)(2 + DEPTH * NODES) * NB * HID];
// per-row ready flags: 4 = ready (4 writer-warp arrivals)
__device__ unsigned g_flag[NFLAGS];

// ---------------- helpers ----------------
__device__ __forceinline__ uint32_t smem_u32(const void* p) {
    uint32_t a;
    asm("{ .reg .u64 t; cvta.to.shared.u64 t, %1; cvt.u32.u64 %0, t; }" : "=r"(a) : "l"(p));
    return a;
}
__device__ __forceinline__ void ldsm4(uint32_t addr, uint32_t r[4]) {
    asm volatile("ldmatrix.sync.aligned.m8n8.x4.shared.b16 {%0,%1,%2,%3}, [%4];"
        : "=r"(r[0]), "=r"(r[1]), "=r"(r[2]), "=r"(r[3]) : "r"(addr));
}
__device__ __forceinline__ void mma16816(float c[4], const uint32_t a[4],
                                         uint32_t b0, uint32_t b1) {
    asm volatile("mma.sync.aligned.m16n8k16.row.col.f32.bf16.bf16.f32 "
        "{%0,%1,%2,%3}, {%4,%5,%6,%7}, {%8,%9}, {%0,%1,%2,%3};"
        : "+f"(c[0]), "+f"(c[1]), "+f"(c[2]), "+f"(c[3])
        : "r"(a[0]), "r"(a[1]), "r"(a[2]), "r"(a[3]), "r"(b0), "r"(b1));
}
__device__ __forceinline__ void named_bar(int id) {
    asm volatile("bar.sync %0, 128;" :: "r"(id) : "memory");
}
// release-reduction publish (orders prior stores, no separate membar)
__device__ __forceinline__ void red_release_add(unsigned* p, unsigned v) {
    asm volatile("red.release.gpu.global.add.u32 [%0], %1;" :: "l"(p), "r"(v) : "memory");
}
// fp32 pair -> bf16 hi word + exact-residual lo word (first elem in low half)
__device__ __forceinline__ void split2(float a, float b, uint32_t& hi, uint32_t& lo) {
    asm("cvt.rn.bf16x2.f32 %0, %1, %2;" : "=r"(hi) : "f"(b), "f"(a));
    float ah = __uint_as_float(hi << 16);
    float bh = __uint_as_float(hi & 0xFFFF0000u);
    float ar = a - ah, br = b - bh;
    asm("cvt.rn.bf16x2.f32 %0, %1, %2;" : "=r"(lo) : "f"(br), "f"(ar));
}
__device__ __forceinline__ float2 unsplit2(uint32_t h, uint32_t l) {
    float ax = __uint_as_float(h << 16) + __uint_as_float(l << 16);
    float ay = __uint_as_float(h & 0xFFFF0000u) + __uint_as_float(l & 0xFFFF0000u);
    return make_float2(ax, ay);
}

// ---------------- smem layout ----------------
#define TILE_B  (128 * STRB)              // 34816
#define SM_W1HI 0
#define SM_W1LO (1 * TILE_B)
#define SM_W2HI (2 * TILE_B)
#define SM_W2LO (3 * TILE_B)
#define SM_AHI  (4 * TILE_B)              // A tile (pv split), then H tile
#define SM_ALO  (5 * TILE_B)
#define SM_B2   (6 * TILE_B)              // 512 B
#define SMEM_TOTAL (6 * TILE_B + 512)

// fused 3-term split GEMM for a 32x32 warp tile:
// acc += Ahi*Bhi + Alo*Bhi + Ahi*Blo  (K=128)
__device__ __forceinline__ void gemm3(uint32_t AhiB, uint32_t AloB,
                                      uint32_t BhiB, uint32_t BloB,
                                      int r0, int c0, int lane,
                                      float acc[2][4][4]) {
    const uint32_t rsel = (uint32_t)(lane & 15);
    const uint32_t ksel = (uint32_t)(lane >> 4) * 16;
    const uint32_t aoff = (r0 + rsel) * STRB + ksel;
    const uint32_t boff = (c0 + rsel) * STRB + ksel;
    uint32_t ah0 = AhiB + aoff, ah1 = ah0 + 16 * STRB;
    uint32_t al0 = AloB + aoff, al1 = al0 + 16 * STRB;
    uint32_t bh0 = BhiB + boff, bh1 = bh0 + 16 * STRB;
    uint32_t bl0 = BloB + boff, bl1 = bl0 + 16 * STRB;
#pragma unroll
    for (int kc = 0; kc < 8; kc++) {
        const uint32_t kb = kc * 32;
        uint32_t Ah0[4], Ah1[4], Al0[4], Al1[4];
        uint32_t Bh0[4], Bh1[4], Bl0[4], Bl1[4];
        ldsm4(ah0 + kb, Ah0); ldsm4(ah1 + kb, Ah1);
        ldsm4(bh0 + kb, Bh0); ldsm4(bh1 + kb, Bh1);
        ldsm4(al0 + kb, Al0); ldsm4(al1 + kb, Al1);
        ldsm4(bl0 + kb, Bl0); ldsm4(bl1 + kb, Bl1);
        mma16816(acc[0][0], Ah0, Bh0[0], Bh0[2]);
        mma16816(acc[0][1], Ah0, Bh0[1], Bh0[3]);
        mma16816(acc[0][2], Ah0, Bh1[0], Bh1[2]);
        mma16816(acc[0][3], Ah0, Bh1[1], Bh1[3]);
        mma16816(acc[1][0], Ah1, Bh0[0], Bh0[2]);
        mma16816(acc[1][1], Ah1, Bh0[1], Bh0[3]);
        mma16816(acc[1][2], Ah1, Bh1[0], Bh1[2]);
        mma16816(acc[1][3], Ah1, Bh1[1], Bh1[3]);
        mma16816(acc[0][0], Al0, Bh0[0], Bh0[2]);
        mma16816(acc[0][1], Al0, Bh0[1], Bh0[3]);
        mma16816(acc[0][2], Al0, Bh1[0], Bh1[2]);
        mma16816(acc[0][3], Al0, Bh1[1], Bh1[3]);
        mma16816(acc[1][0], Al1, Bh0[0], Bh0[2]);
        mma16816(acc[1][1], Al1, Bh0[1], Bh0[3]);
        mma16816(acc[1][2], Al1, Bh1[0], Bh1[2]);
        mma16816(acc[1][3], Al1, Bh1[1], Bh1[3]);
        mma16816(acc[0][0], Ah0, Bl0[0], Bl0[2]);
        mma16816(acc[0][1], Ah0, Bl0[1], Bl0[3]);
        mma16816(acc[0][2], Ah0, Bl1[0], Bl1[2]);
        mma16816(acc[0][3], Ah0, Bl1[1], Bl1[3]);
        mma16816(acc[1][0], Ah1, Bl0[0], Bl0[2]);
        mma16816(acc[1][1], Ah1, Bl0[1], Bl0[3]);
        mma16816(acc[1][2], Ah1, Bl1[0], Bl1[2]);
        mma16816(acc[1][3], Ah1, Bl1[1], Bl1[3]);
    }
}

// ---------------- prep ----------------
__global__ void prep_kernel(const float* __restrict__ emb,
                            const float* __restrict__ W1,
                            const float* __restrict__ W2,
                            float* __restrict__ out) {
    int n = blockIdx.x, tid = threadIdx.x;  // 128 x 256
    for (int k = tid; k < 192; k += 256) {
        float v = W1[n * 192 + k];
        if (k < 128) {
            __nv_bfloat16 h = __float2bfloat16(v);
            g_w1hi[n * HID + k] = h;
            g_w1lo[n * HID + k] = __float2bfloat16(v - __bfloat162float(h));
        } else {
            g_W1bT[(k - 128) * HID + n] = v;
        }
    }
    for (int k = tid; k < 128; k += 256) {
        float v = W2[n * HID + k];
        __nv_bfloat16 h = __float2bfloat16(v);
        g_w2hi[n * HID + k] = h;
        g_w2lo[n * HID + k] = __float2bfloat16(v - __bfloat162float(h));
    }
    int g = n * 256 + tid;
    if (g < NB * HID) {
        int b = g >> 7, c = g & 127;
        out[(size_t)b * ROWS_PER_B * HID + c] = emb[g];
        g_buf[(size_t)b * HID + c] = emb[g];      // g_row 0 = root
    }
    if (n == 0) {
        float* zr = g_buf + (size_t)ZROW * NB * HID;
        for (int i = tid; i < NB * HID; i += 256) zr[i] = 0.f;
        for (int i = tid; i < NFLAGS; i += 256)
            g_flag[i] = (i == 0 || i == ZROW) ? 4u : 0u;
    }
}

// ---------------- c_pre = W1b @ ne + b1 ----------------
__global__ __launch_bounds__(256) void cpre_kernel(const float* __restrict__ emb_table,
                                                   const float* __restrict__ b1) {
    __shared__ float sne[32][64];
    __shared__ float sw[64][128];
    int tid = threadIdx.x;
    int row0 = blockIdx.x * 32;
    for (int i = tid; i < 32 * 64; i += 256) {
        int r = i >> 6, e = i & 63;
        sne[r][e] = emb_table[(size_t)(2 + row0 + r) * 64 + e];
    }
    for (int i = tid; i < 64 * 128; i += 256)
        sw[i >> 7][i & 127] = g_W1bT[i];
    __syncthreads();
    int c = tid & 127;
    int rh = (tid >> 7) * 16;
    float acc[16];
    float bv = b1[c];
#pragma unroll
    for (int rr = 0; rr < 16; rr++) acc[rr] = bv;
    for (int k = 0; k < 64; k++) {
        float w = sw[k][c];
#pragma unroll
        for (int rr = 0; rr < 16; rr++) acc[rr] += sne[rh + rr][k] * w;
    }
#pragma unroll
    for (int rr = 0; rr < 16; rr++)
        g_cpre[(size_t)(row0 + rh + rr) * HID + c] = acc[rr];
}

// ---------------- persistent DAG kernel: 4 autonomous warpgroups ----------------
__global__ __launch_bounds__(NTHREADS, 1)
void dag_kernel(float* __restrict__ out, const int* __restrict__ pidx,
                const float* __restrict__ b2) {
    extern __shared__ char smc[];
    const uint32_t sb = smem_u32(smc);
    const int tid = threadIdx.x;
    const int wid = tid >> 5, lane = tid & 31;
    const int n0 = blockIdx.x * 4;

    const int nn = wid >> 2;            // warpgroup = node index within CTA
    const int cw = wid & 3;             // warp-in-group = column group
    const int node = n0 + nn;
    const int r0 = nn * 32;             // this node's tile rows
    const int c0 = cw * 32;             // this warp's output columns
    const int bbase = cw * 8;           // gather batch base
    const int barid = 1 + nn;           // named barrier id (1..4)
    const int tq = lane >> 2;
    const int tc = (lane & 3) * 2;

    // one-time: stationary W1/W2 tiles + b2
    {
        const uint2* w1h = (const uint2*)g_w1hi;
        const uint2* w1l = (const uint2*)g_w1lo;
        const uint2* w2h = (const uint2*)g_w2hi;
        const uint2* w2l = (const uint2*)g_w2lo;
        for (int i = tid; i < 128 * 32; i += NTHREADS) {
            int r = i >> 5, q = i & 31;
            uint32_t off = (uint32_t)r * STRB + q * 8;
            *(uint2*)(smc + SM_W1HI + off) = w1h[i];
            *(uint2*)(smc + SM_W1LO + off) = w1l[i];
            *(uint2*)(smc + SM_W2HI + off) = w2h[i];
            *(uint2*)(smc + SM_W2LO + off) = w2l[i];
        }
        if (tid < 128) ((float*)(smc + SM_B2))[tid] = b2[tid];
    }
    __syncthreads();
    const float* s_b2 = (const float*)(smc + SM_B2);

    for (int d = 0; d < DEPTH; d++) {
        const int orow = 1 + d * NODES + node;   // out row == g_buf row

        // ---- gather: pidx load, poll parent flags, sum, split -> A tiles ----
        {
            int prow = -1;
            if (lane < NPAR) {
                int s = __ldg(&pidx[(d * NODES + node) * NPAR + lane]);
                prow = s ? (s - 1) : -1;
                if (prow >= 0) {
                    volatile unsigned* f = &g_flag[prow];
                    while (*f < 4u) __nanosleep(32);
                }
            }
            __syncwarp();      // all lanes past the poll; rows written-once => no stale L1
            float vx[8], vy[8], vz[8], vw[8];
#pragma unroll
            for (int rr = 0; rr < 8; rr++) { vx[rr] = 0.f; vy[rr] = 0.f; vz[rr] = 0.f; vw[rr] = 0.f; }
#pragma unroll
            for (int p = 0; p < NPAR; p++) {
                int row = __shfl_sync(0xFFFFFFFFu, prow, p);
                if (row < 0) continue;          // warp-uniform skip
                const float* pb = g_buf + (size_t)row * (NB * HID)
                                + (size_t)bbase * HID + lane * 4;
#pragma unroll
                for (int rr = 0; rr < 8; rr++) {
                    float4 v = *(const float4*)(pb + (size_t)rr * HID);
                    vx[rr] += v.x; vy[rr] += v.y; vz[rr] += v.z; vw[rr] += v.w;
                }
            }
#pragma unroll
            for (int rr = 0; rr < 8; rr++) {
                int r = r0 + bbase + rr;
                uint32_t h0, l0, h1, l1;
                split2(vx[rr], vy[rr], h0, l0);
                split2(vz[rr], vw[rr], h1, l1);
                uint32_t o = (uint32_t)r * STRB + lane * 8;
                *(uint32_t*)(smc + SM_AHI + o) = h0;
                *(uint32_t*)(smc + SM_AHI + o + 4) = h1;
                *(uint32_t*)(smc + SM_ALO + o) = l0;
                *(uint32_t*)(smc + SM_ALO + o + 4) = l1;
            }
        }
        named_bar(barid);      // bar1: A tile (pv split) visible within group

        float acc[2][4][4];
#pragma unroll
        for (int mt = 0; mt < 2; mt++)
#pragma unroll
            for (int nt = 0; nt < 4; nt++)
#pragma unroll
                for (int q = 0; q < 4; q++) acc[mt][nt][q] = 0.f;

        // ---- GEMM1: A x W1 ----
        gemm3(sb + SM_AHI, sb + SM_ALO, sb + SM_W1HI, sb + SM_W1LO, r0, c0, lane, acc);

        // ---- seed GEMM2 accumulator with pv (from A tiles) + b2 ----
        float acc2[2][4][4];
#pragma unroll
        for (int nt = 0; nt < 4; nt++) {
            int c = c0 + nt * 8 + tc;
            float2 b2v = *(const float2*)(s_b2 + c);
#pragma unroll
            for (int mt = 0; mt < 2; mt++) {
#pragma unroll
                for (int half = 0; half < 2; half++) {
                    int b = mt * 16 + tq + half * 8;
                    int rA = r0 + b;
                    uint32_t off = (uint32_t)rA * STRB + c * 2;
                    float2 pvv = unsplit2(*(const uint32_t*)(smc + SM_AHI + off),
                                          *(const uint32_t*)(smc + SM_ALO + off));
                    acc2[mt][nt][half * 2 + 0] = pvv.x + b2v.x;
                    acc2[mt][nt][half * 2 + 1] = pvv.y + b2v.y;
                }
            }
        }
        named_bar(barid);      // bar2: all A reads (GEMM1 + seed) done

        // ---- relu(D1 + cpre) -> split -> H (A region) ----
        {
            const float* cp = g_cpre + (size_t)(d * NODES + node) * HID;
#pragma unroll
            for (int mt = 0; mt < 2; mt++) {
#pragma unroll
                for (int nt = 0; nt < 4; nt++) {
                    int c = c0 + nt * 8 + tc;
                    float2 cpv = *(const float2*)(cp + c);
                    float v0 = fmaxf(acc[mt][nt][0] + cpv.x, 0.f);
                    float v1 = fmaxf(acc[mt][nt][1] + cpv.y, 0.f);
                    float v2 = fmaxf(acc[mt][nt][2] + cpv.x, 0.f);
                    float v3 = fmaxf(acc[mt][nt][3] + cpv.y, 0.f);
                    uint32_t hi, lo;
                    uint32_t oA = (uint32_t)(r0 + mt * 16 + tq) * STRB + c * 2;
                    uint32_t oB = oA + 8 * STRB;
                    split2(v0, v1, hi, lo);
                    *(uint32_t*)(smc + SM_AHI + oA) = hi;
                    *(uint32_t*)(smc + SM_ALO + oA) = lo;
                    split2(v2, v3, hi, lo);
                    *(uint32_t*)(smc + SM_AHI + oB) = hi;
                    *(uint32_t*)(smc + SM_ALO + oB) = lo;
                }
            }
        }
        named_bar(barid);      // bar3: H visible within group

        // ---- GEMM2: acc2(pv + b2) += H x W2 ----
        gemm3(sb + SM_AHI, sb + SM_ALO, sb + SM_W2HI, sb + SM_W2LO, r0, c0, lane, acc2);

        if (d + 1 < DEPTH) {
            // ---- g_buf first (the chain), release-publish, THEN out ----
#pragma unroll
            for (int mt = 0; mt < 2; mt++) {
#pragma unroll
                for (int half = 0; half < 2; half++) {
                    int b = mt * 16 + tq + half * 8;
                    float* pg = g_buf + ((size_t)orow * NB + b) * HID;
#pragma unroll
                    for (int nt = 0; nt < 4; nt++) {
                        int c = c0 + nt * 8 + tc;
                        *(float2*)(pg + c) = make_float2(acc2[mt][nt][half * 2 + 0],
                                                         acc2[mt][nt][half * 2 + 1]);
                    }
                }
            }
            __syncwarp();
            if (lane == 0) red_release_add(&g_flag[orow], 1u);
            // out writes (not consumed by anyone)
#pragma unroll
            for (int mt = 0; mt < 2; mt++) {
#pragma unroll
                for (int half = 0; half < 2; half++) {
                    int b = mt * 16 + tq + half * 8;
                    float* po = out + ((size_t)b * ROWS_PER_B + orow) * HID;
#pragma unroll
                    for (int nt = 0; nt < 4; nt++) {
                        int c = c0 + nt * 8 + tc;
                        *(float2*)(po + c) = make_float2(acc2[mt][nt][half * 2 + 0],
                                                         acc2[mt][nt][half * 2 + 1]);
                    }
                }
            }
            named_bar(barid);      // bar4: group GEMM2 reads done; A/H reusable
        } else {
            // last depth: out only
#pragma unroll
            for (int mt = 0; mt < 2; mt++) {
#pragma unroll
                for (int half = 0; half < 2; half++) {
                    int b = mt * 16 + tq + half * 8;
                    float* po = out + ((size_t)b * ROWS_PER_B + orow) * HID;
#pragma unroll
                    for (int nt = 0; nt < 4; nt++) {
                        int c = c0 + nt * 8 + tc;
                        *(float2*)(po + c) = make_float2(acc2[mt][nt][half * 2 + 0],
                                                         acc2[mt][nt][half * 2 + 1]);
                    }
                }
            }
        }
    }
}

extern "C" void kernel_launch(void* const* d_in, const int* in_sizes, int n_in,
                              void* d_out, int out_size) {
    const float* embedding  = (const float*)d_in[0];
    const float* emb_table  = (const float*)d_in[1];
    const float* W1         = (const float*)d_in[2];
    const float* b1         = (const float*)d_in[3];
    const float* W2         = (const float*)d_in[4];
    const float* b2         = (const float*)d_in[5];
    const int*   parent_idx = (const int*)d_in[6];
    float* out = (float*)d_out;
    (void)in_sizes; (void)n_in; (void)out_size;

    cudaFuncSetAttribute(dag_kernel,
                         cudaFuncAttributeMaxDynamicSharedMemorySize, SMEM_TOTAL);

    prep_kernel<<<128, 256>>>(embedding, W1, W2, out);
    cpre_kernel<<<DEPTH * NODES / 32, 256>>>(emb_table, b1);
    dag_kernel<<<128, NTHREADS, SMEM_TOTAL>>>(out, parent_idx, b2);
}

// round 16
// speedup vs baseline: 1.4014x; 1.0011x over previous
#include <cuda_runtime.h>
#include <cuda_bf16.h>
#include <cstdint>

#define DEPTH 32
#define NODES 512
#define NPAR 8
#define NB 32
#define HID 128
#define ROWS_PER_B 16385
#define STRB 272            // smem tile row stride bytes (136 bf16)
#define NTHREADS 512
#define ZROW 16385
#define NFLAGS 16386

// ---------------- device statics ----------------
__device__ float g_cpre[DEPTH * NODES * HID];
__device__ __nv_bfloat16 g_w1hi[HID * HID], g_w1lo[HID * HID];  // [n][k]
__device__ __nv_bfloat16 g_w2hi[HID * HID], g_w2lo[HID * HID];  // [n][k]
__device__ float g_buf[(size_t)(2 + DEPTH * NODES) * NB * HID];
// per-row ready flags: 4 = ready (4 writer-warp arrivals)
__device__ unsigned g_flag[NFLAGS];

// ---------------- helpers ----------------
__device__ __forceinline__ uint32_t smem_u32(const void* p) {
    uint32_t a;
    asm("{ .reg .u64 t; cvta.to.shared.u64 t, %1; cvt.u32.u64 %0, t; }" : "=r"(a) : "l"(p));
    return a;
}
__device__ __forceinline__ void ldsm4(uint32_t addr, uint32_t r[4]) {
    asm volatile("ldmatrix.sync.aligned.m8n8.x4.shared.b16 {%0,%1,%2,%3}, [%4];"
        : "=r"(r[0]), "=r"(r[1]), "=r"(r[2]), "=r"(r[3]) : "r"(addr));
}
__device__ __forceinline__ void mma16816(float c[4], const uint32_t a[4],
                                         uint32_t b0, uint32_t b1) {
    asm volatile("mma.sync.aligned.m16n8k16.row.col.f32.bf16.bf16.f32 "
        "{%0,%1,%2,%3}, {%4,%5,%6,%7}, {%8,%9}, {%0,%1,%2,%3};"
        : "+f"(c[0]), "+f"(c[1]), "+f"(c[2]), "+f"(c[3])
        : "r"(a[0]), "r"(a[1]), "r"(a[2]), "r"(a[3]), "r"(b0), "r"(b1));
}
__device__ __forceinline__ void named_bar(int id) {
    asm volatile("bar.sync %0, 128;" :: "r"(id) : "memory");
}
__device__ __forceinline__ void red_release_add(unsigned* p, unsigned v) {
    asm volatile("red.release.gpu.global.add.u32 [%0], %1;" :: "l"(p), "r"(v) : "memory");
}
// fp32 pair -> bf16 hi word + exact-residual lo word (first elem in low half)
__device__ __forceinline__ void split2(float a, float b, uint32_t& hi, uint32_t& lo) {
    asm("cvt.rn.bf16x2.f32 %0, %1, %2;" : "=r"(hi) : "f"(b), "f"(a));
    float ah = __uint_as_float(hi << 16);
    float bh = __uint_as_float(hi & 0xFFFF0000u);
    float ar = a - ah, br = b - bh;
    asm("cvt.rn.bf16x2.f32 %0, %1, %2;" : "=r"(lo) : "f"(br), "f"(ar));
}
__device__ __forceinline__ float2 unsplit2(uint32_t h, uint32_t l) {
    float ax = __uint_as_float(h << 16) + __uint_as_float(l << 16);
    float ay = __uint_as_float(h & 0xFFFF0000u) + __uint_as_float(l & 0xFFFF0000u);
    return make_float2(ax, ay);
}

// ---------------- smem layout ----------------
#define TILE_B  (128 * STRB)              // 34816
#define SM_W1HI 0
#define SM_W1LO (1 * TILE_B)
#define SM_W2HI (2 * TILE_B)
#define SM_W2LO (3 * TILE_B)
#define SM_AHI  (4 * TILE_B)              // A tile (pv split), then H tile
#define SM_ALO  (5 * TILE_B)
#define SM_B2   (6 * TILE_B)              // 512 B
#define SMEM_TOTAL (6 * TILE_B + 512)

// fused 3-term split GEMM for a 32x32 warp tile:
// acc += Ahi*Bhi + Alo*Bhi + Ahi*Blo  (K=128)
__device__ __forceinline__ void gemm3(uint32_t AhiB, uint32_t AloB,
                                      uint32_t BhiB, uint32_t BloB,
                                      int r0, int c0, int lane,
                                      float acc[2][4][4]) {
    const uint32_t rsel = (uint32_t)(lane & 15);
    const uint32_t ksel = (uint32_t)(lane >> 4) * 16;
    const uint32_t aoff = (r0 + rsel) * STRB + ksel;
    const uint32_t boff = (c0 + rsel) * STRB + ksel;
    uint32_t ah0 = AhiB + aoff, ah1 = ah0 + 16 * STRB;
    uint32_t al0 = AloB + aoff, al1 = al0 + 16 * STRB;
    uint32_t bh0 = BhiB + boff, bh1 = bh0 + 16 * STRB;
    uint32_t bl0 = BloB + boff, bl1 = bl0 + 16 * STRB;
#pragma unroll
    for (int kc = 0; kc < 8; kc++) {
        const uint32_t kb = kc * 32;
        uint32_t Ah0[4], Ah1[4], Al0[4], Al1[4];
        uint32_t Bh0[4], Bh1[4], Bl0[4], Bl1[4];
        ldsm4(ah0 + kb, Ah0); ldsm4(ah1 + kb, Ah1);
        ldsm4(bh0 + kb, Bh0); ldsm4(bh1 + kb, Bh1);
        ldsm4(al0 + kb, Al0); ldsm4(al1 + kb, Al1);
        ldsm4(bl0 + kb, Bl0); ldsm4(bl1 + kb, Bl1);
        mma16816(acc[0][0], Ah0, Bh0[0], Bh0[2]);
        mma16816(acc[0][1], Ah0, Bh0[1], Bh0[3]);
        mma16816(acc[0][2], Ah0, Bh1[0], Bh1[2]);
        mma16816(acc[0][3], Ah0, Bh1[1], Bh1[3]);
        mma16816(acc[1][0], Ah1, Bh0[0], Bh0[2]);
        mma16816(acc[1][1], Ah1, Bh0[1], Bh0[3]);
        mma16816(acc[1][2], Ah1, Bh1[0], Bh1[2]);
        mma16816(acc[1][3], Ah1, Bh1[1], Bh1[3]);
        mma16816(acc[0][0], Al0, Bh0[0], Bh0[2]);
        mma16816(acc[0][1], Al0, Bh0[1], Bh0[3]);
        mma16816(acc[0][2], Al0, Bh1[0], Bh1[2]);
        mma16816(acc[0][3], Al0, Bh1[1], Bh1[3]);
        mma16816(acc[1][0], Al1, Bh0[0], Bh0[2]);
        mma16816(acc[1][1], Al1, Bh0[1], Bh0[3]);
        mma16816(acc[1][2], Al1, Bh1[0], Bh1[2]);
        mma16816(acc[1][3], Al1, Bh1[1], Bh1[3]);
        mma16816(acc[0][0], Ah0, Bl0[0], Bl0[2]);
        mma16816(acc[0][1], Ah0, Bl0[1], Bl0[3]);
        mma16816(acc[0][2], Ah0, Bl1[0], Bl1[2]);
        mma16816(acc[0][3], Ah0, Bl1[1], Bl1[3]);
        mma16816(acc[1][0], Ah1, Bl0[0], Bl0[2]);
        mma16816(acc[1][1], Ah1, Bl0[1], Bl0[3]);
        mma16816(acc[1][2], Ah1, Bl1[0], Bl1[2]);
        mma16816(acc[1][3], Ah1, Bl1[1], Bl1[3]);
    }
}

// ---------------- prep: weight splits + cpre + roots + flags (single kernel) ----------------
// grid 512 x 256. Blocks 0-127 also do weight splits (neuron = blk).
// All blocks compute cpre rows [blk*32, blk*32+32) directly from W1 gmem.
__global__ __launch_bounds__(256) void prep_kernel(
    const float* __restrict__ emb, const float* __restrict__ emb_table,
    const float* __restrict__ W1, const float* __restrict__ b1,
    const float* __restrict__ W2, float* __restrict__ out) {
    __shared__ float sne[32][64];
    __shared__ float sw[64][128];
    const int blk = blockIdx.x, tid = threadIdx.x;

    // weight splits (blocks 0-127, neuron = blk)
    if (blk < 128) {
        int n = blk;
        for (int k = tid; k < 128; k += 256) {
            float v = W1[n * 192 + k];
            __nv_bfloat16 h = __float2bfloat16(v);
            g_w1hi[n * HID + k] = h;
            g_w1lo[n * HID + k] = __float2bfloat16(v - __bfloat162float(h));
            float v2 = W2[n * HID + k];
            __nv_bfloat16 h2 = __float2bfloat16(v2);
            g_w2hi[n * HID + k] = h2;
            g_w2lo[n * HID + k] = __float2bfloat16(v2 - __bfloat162float(h2));
        }
        int g = n * 256 + tid;
        if (g < NB * HID) {
            int b = g >> 7, c = g & 127;
            out[(size_t)b * ROWS_PER_B * HID + c] = emb[g];
            g_buf[(size_t)b * HID + c] = emb[g];      // g_row 0 = root
        }
        if (n == 0) {
            float* zr = g_buf + (size_t)ZROW * NB * HID;
            for (int i = tid; i < NB * HID; i += 256) zr[i] = 0.f;
            for (int i = tid; i < NFLAGS; i += 256)
                g_flag[i] = (i == 0 || i == ZROW) ? 4u : 0u;
        }
    }

    // cpre rows for this block: row0 = blk*32
    const int row0 = blk * 32;
    for (int i = tid; i < 32 * 64; i += 256) {
        int r = i >> 6, e = i & 63;
        sne[r][e] = emb_table[(size_t)(2 + row0 + r) * 64 + e];
    }
    // sw[k][c] = W1[c][128+k]
    for (int i = tid; i < 128 * 64; i += 256) {
        int c = i >> 6, k = i & 63;
        sw[k][c] = W1[c * 192 + 128 + k];
    }
    __syncthreads();
    int c = tid & 127;
    int rh = (tid >> 7) * 16;
    float acc[16];
    float bv = b1[c];
#pragma unroll
    for (int rr = 0; rr < 16; rr++) acc[rr] = bv;
    for (int k = 0; k < 64; k++) {
        float w = sw[k][c];
#pragma unroll
        for (int rr = 0; rr < 16; rr++) acc[rr] += sne[rh + rr][k] * w;
    }
#pragma unroll
    for (int rr = 0; rr < 16; rr++)
        g_cpre[(size_t)(row0 + rh + rr) * HID + c] = acc[rr];
}

// ---------------- persistent DAG kernel: 4 autonomous warpgroups ----------------
__global__ __launch_bounds__(NTHREADS, 1)
void dag_kernel(float* __restrict__ out, const int* __restrict__ pidx,
                const float* __restrict__ b2) {
    extern __shared__ char smc[];
    const uint32_t sb = smem_u32(smc);
    const int tid = threadIdx.x;
    const int wid = tid >> 5, lane = tid & 31;
    const int n0 = blockIdx.x * 4;

    const int nn = wid >> 2;            // warpgroup = node index within CTA
    const int cw = wid & 3;             // warp-in-group = column group
    const int node = n0 + nn;
    const int r0 = nn * 32;
    const int c0 = cw * 32;
    const int bbase = cw * 8;
    const int barid = 1 + nn;
    const int tq = lane >> 2;
    const int tc = (lane & 3) * 2;

    // one-time: stationary W1/W2 tiles + b2
    {
        const uint2* w1h = (const uint2*)g_w1hi;
        const uint2* w1l = (const uint2*)g_w1lo;
        const uint2* w2h = (const uint2*)g_w2hi;
        const uint2* w2l = (const uint2*)g_w2lo;
        for (int i = tid; i < 128 * 32; i += NTHREADS) {
            int r = i >> 5, q = i & 31;
            uint32_t off = (uint32_t)r * STRB + q * 8;
            *(uint2*)(smc + SM_W1HI + off) = w1h[i];
            *(uint2*)(smc + SM_W1LO + off) = w1l[i];
            *(uint2*)(smc + SM_W2HI + off) = w2h[i];
            *(uint2*)(smc + SM_W2LO + off) = w2l[i];
        }
        if (tid < 128) ((float*)(smc + SM_B2))[tid] = b2[tid];
    }
    __syncthreads();
    const float* s_b2 = (const float*)(smc + SM_B2);

    // pidx for depth 0 (hoisted; subsequent depths loaded before bar4)
    int s_par = (lane < NPAR) ? __ldg(&pidx[node * NPAR + lane]) : 0;

    for (int d = 0; d < DEPTH; d++) {
        const int orow = 1 + d * NODES + node;   // out row == g_buf row

        // ---- gather: poll parent flags, sum, split -> A tiles ----
        {
            int prow = -1;
            if (lane < NPAR) {
                prow = s_par ? (s_par - 1) : -1;
                if (prow >= 0) {
                    volatile unsigned* f = &g_flag[prow];
                    while (*f < 4u) __nanosleep(32);
                }
            }
            __syncwarp();      // rows written-once => no stale L1 possible
            float vx[8], vy[8], vz[8], vw[8];
#pragma unroll
            for (int rr = 0; rr < 8; rr++) { vx[rr] = 0.f; vy[rr] = 0.f; vz[rr] = 0.f; vw[rr] = 0.f; }
#pragma unroll
            for (int p = 0; p < NPAR; p++) {
                int row = __shfl_sync(0xFFFFFFFFu, prow, p);
                if (row < 0) continue;          // warp-uniform skip
                const float* pb = g_buf + (size_t)row * (NB * HID)
                                + (size_t)bbase * HID + lane * 4;
#pragma unroll
                for (int rr = 0; rr < 8; rr++) {
                    float4 v = *(const float4*)(pb + (size_t)rr * HID);
                    vx[rr] += v.x; vy[rr] += v.y; vz[rr] += v.z; vw[rr] += v.w;
                }
            }
#pragma unroll
            for (int rr = 0; rr < 8; rr++) {
                int r = r0 + bbase + rr;
                uint32_t h0, l0, h1, l1;
                split2(vx[rr], vy[rr], h0, l0);
                split2(vz[rr], vw[rr], h1, l1);
                uint32_t o = (uint32_t)r * STRB + lane * 8;
                *(uint32_t*)(smc + SM_AHI + o) = h0;
                *(uint32_t*)(smc + SM_AHI + o + 4) = h1;
                *(uint32_t*)(smc + SM_ALO + o) = l0;
                *(uint32_t*)(smc + SM_ALO + o + 4) = l1;
            }
        }
        named_bar(barid);      // bar1: A tile (pv split) visible within group

        float acc[2][4][4];
#pragma unroll
        for (int mt = 0; mt < 2; mt++)
#pragma unroll
            for (int nt = 0; nt < 4; nt++)
#pragma unroll
                for (int q = 0; q < 4; q++) acc[mt][nt][q] = 0.f;

        // ---- GEMM1: A x W1 ----
        gemm3(sb + SM_AHI, sb + SM_ALO, sb + SM_W1HI, sb + SM_W1LO, r0, c0, lane, acc);

        // ---- seed GEMM2 accumulator with pv (from A tiles) + b2 ----
        float acc2[2][4][4];
#pragma unroll
        for (int nt = 0; nt < 4; nt++) {
            int c = c0 + nt * 8 + tc;
            float2 b2v = *(const float2*)(s_b2 + c);
#pragma unroll
            for (int mt = 0; mt < 2; mt++) {
#pragma unroll
                for (int half = 0; half < 2; half++) {
                    int b = mt * 16 + tq + half * 8;
                    int rA = r0 + b;
                    uint32_t off = (uint32_t)rA * STRB + c * 2;
                    float2 pvv = unsplit2(*(const uint32_t*)(smc + SM_AHI + off),
                                          *(const uint32_t*)(smc + SM_ALO + off));
                    acc2[mt][nt][half * 2 + 0] = pvv.x + b2v.x;
                    acc2[mt][nt][half * 2 + 1] = pvv.y + b2v.y;
                }
            }
        }
        named_bar(barid);      // bar2: all A reads (GEMM1 + seed) done

        // ---- relu(D1 + cpre) -> split -> H (A region) ----
        {
            const float* cp = g_cpre + (size_t)(d * NODES + node) * HID;
#pragma unroll
            for (int mt = 0; mt < 2; mt++) {
#pragma unroll
                for (int nt = 0; nt < 4; nt++) {
                    int c = c0 + nt * 8 + tc;
                    float2 cpv = *(const float2*)(cp + c);
                    float v0 = fmaxf(acc[mt][nt][0] + cpv.x, 0.f);
                    float v1 = fmaxf(acc[mt][nt][1] + cpv.y, 0.f);
                    float v2 = fmaxf(acc[mt][nt][2] + cpv.x, 0.f);
                    float v3 = fmaxf(acc[mt][nt][3] + cpv.y, 0.f);
                    uint32_t hi, lo;
                    uint32_t oA = (uint32_t)(r0 + mt * 16 + tq) * STRB + c * 2;
                    uint32_t oB = oA + 8 * STRB;
                    split2(v0, v1, hi, lo);
                    *(uint32_t*)(smc + SM_AHI + oA) = hi;
                    *(uint32_t*)(smc + SM_ALO + oA) = lo;
                    split2(v2, v3, hi, lo);
                    *(uint32_t*)(smc + SM_AHI + oB) = hi;
                    *(uint32_t*)(smc + SM_ALO + oB) = lo;
                }
            }
        }
        named_bar(barid);      // bar3: H visible within group

        // ---- GEMM2: acc2(pv + b2) += H x W2 ----
        gemm3(sb + SM_AHI, sb + SM_ALO, sb + SM_W2HI, sb + SM_W2LO, r0, c0, lane, acc2);

        if (d + 1 < DEPTH) {
            // ---- g_buf first (the chain), release-publish, THEN out ----
#pragma unroll
            for (int mt = 0; mt < 2; mt++) {
#pragma unroll
                for (int half = 0; half < 2; half++) {
                    int b = mt * 16 + tq + half * 8;
                    float* pg = g_buf + ((size_t)orow * NB + b) * HID;
#pragma unroll
                    for (int nt = 0; nt < 4; nt++) {
                        int c = c0 + nt * 8 + tc;
                        *(float2*)(pg + c) = make_float2(acc2[mt][nt][half * 2 + 0],
                                                         acc2[mt][nt][half * 2 + 1]);
                    }
                }
            }
            __syncwarp();
            if (lane == 0) red_release_add(&g_flag[orow], 1u);
            // out writes (not consumed by anyone)
#pragma unroll
            for (int mt = 0; mt < 2; mt++) {
#pragma unroll
                for (int half = 0; half < 2; half++) {
                    int b = mt * 16 + tq + half * 8;
                    float* po = out + ((size_t)b * ROWS_PER_B + orow) * HID;
#pragma unroll
                    for (int nt = 0; nt < 4; nt++) {
                        int c = c0 + nt * 8 + tc;
                        *(float2*)(po + c) = make_float2(acc2[mt][nt][half * 2 + 0],
                                                         acc2[mt][nt][half * 2 + 1]);
                    }
                }
            }
            // prefetch next depth's parent slots (latency hidden behind bar4)
            if (lane < NPAR)
                s_par = __ldg(&pidx[((d + 1) * NODES + node) * NPAR + lane]);
            named_bar(barid);      // bar4: group GEMM2 reads done; A/H reusable
        } else {
            // last depth: out only
#pragma unroll
            for (int mt = 0; mt < 2; mt++) {
#pragma unroll
                for (int half = 0; half < 2; half++) {
                    int b = mt * 16 + tq + half * 8;
                    float* po = out + ((size_t)b * ROWS_PER_B + orow) * HID;
#pragma unroll
                    for (int nt = 0; nt < 4; nt++) {
                        int c = c0 + nt * 8 + tc;
                        *(float2*)(po + c) = make_float2(acc2[mt][nt][half * 2 + 0],
                                                         acc2[mt][nt][half * 2 + 1]);
                    }
                }
            }
        }
    }
}

extern "C" void kernel_launch(void* const* d_in, const int* in_sizes, int n_in,
                              void* d_out, int out_size) {
    const float* embedding  = (const float*)d_in[0];
    const float* emb_table  = (const float*)d_in[1];
    const float* W1         = (const float*)d_in[2];
    const float* b1         = (const float*)d_in[3];
    const float* W2         = (const float*)d_in[4];
    const float* b2         = (const float*)d_in[5];
    const int*   parent_idx = (const int*)d_in[6];
    float* out = (float*)d_out;
    (void)in_sizes; (void)n_in; (void)out_size;

    cudaFuncSetAttribute(dag_kernel,
                         cudaFuncAttributeMaxDynamicSharedMemorySize, SMEM_TOTAL);

    prep_kernel<<<DEPTH * NODES / 32, 256>>>(embedding, emb_table, W1, b1, W2, out);
    dag_kernel<<<128, NTHREADS, SMEM_TOTAL>>>(out, parent_idx, b2);
}

// round 17
// speedup vs baseline: 1.4381x; 1.0262x over previous
#include <cuda_runtime.h>
#include <cuda_bf16.h>
#include <cstdint>

#define DEPTH 32
#define NODES 512
#define NPAR 8
#define NB 32
#define HID 128
#define ROWS_PER_B 16385
#define STRB 272            // smem tile row stride bytes (136 bf16)
#define NTHREADS 512
#define NFLAGS 16385

// ---------------- device statics ----------------
__device__ float g_cpre[DEPTH * NODES * HID];
__device__ __nv_bfloat16 g_w1hi[HID * HID], g_w1lo[HID * HID];  // [n][k]
__device__ __nv_bfloat16 g_w2hi[HID * HID], g_w2lo[HID * HID];  // [n][k]
// per-row ready flags: 4 = ready (4 writer-warp arrivals); row = out row index
__device__ unsigned g_flag[NFLAGS];

// ---------------- helpers ----------------
__device__ __forceinline__ uint32_t smem_u32(const void* p) {
    uint32_t a;
    asm("{ .reg .u64 t; cvta.to.shared.u64 t, %1; cvt.u32.u64 %0, t; }" : "=r"(a) : "l"(p));
    return a;
}
__device__ __forceinline__ void ldsm4(uint32_t addr, uint32_t r[4]) {
    asm volatile("ldmatrix.sync.aligned.m8n8.x4.shared.b16 {%0,%1,%2,%3}, [%4];"
        : "=r"(r[0]), "=r"(r[1]), "=r"(r[2]), "=r"(r[3]) : "r"(addr));
}
__device__ __forceinline__ void mma16816(float c[4], const uint32_t a[4],
                                         uint32_t b0, uint32_t b1) {
    asm volatile("mma.sync.aligned.m16n8k16.row.col.f32.bf16.bf16.f32 "
        "{%0,%1,%2,%3}, {%4,%5,%6,%7}, {%8,%9}, {%0,%1,%2,%3};"
        : "+f"(c[0]), "+f"(c[1]), "+f"(c[2]), "+f"(c[3])
        : "r"(a[0]), "r"(a[1]), "r"(a[2]), "r"(a[3]), "r"(b0), "r"(b1));
}
__device__ __forceinline__ void named_bar(int id) {
    asm volatile("bar.sync %0, 128;" :: "r"(id) : "memory");
}
__device__ __forceinline__ void red_release_add(unsigned* p, unsigned v) {
    asm volatile("red.release.gpu.global.add.u32 [%0], %1;" :: "l"(p), "r"(v) : "memory");
}
// fp32 pair -> bf16 hi word + exact-residual lo word (first elem in low half)
__device__ __forceinline__ void split2(float a, float b, uint32_t& hi, uint32_t& lo) {
    asm("cvt.rn.bf16x2.f32 %0, %1, %2;" : "=r"(hi) : "f"(b), "f"(a));
    float ah = __uint_as_float(hi << 16);
    float bh = __uint_as_float(hi & 0xFFFF0000u);
    float ar = a - ah, br = b - bh;
    asm("cvt.rn.bf16x2.f32 %0, %1, %2;" : "=r"(lo) : "f"(br), "f"(ar));
}
__device__ __forceinline__ float2 unsplit2(uint32_t h, uint32_t l) {
    float ax = __uint_as_float(h << 16) + __uint_as_float(l << 16);
    float ay = __uint_as_float(h & 0xFFFF0000u) + __uint_as_float(l & 0xFFFF0000u);
    return make_float2(ax, ay);
}

// ---------------- smem layout ----------------
#define TILE_B  (128 * STRB)              // 34816
#define SM_W1HI 0
#define SM_W1LO (1 * TILE_B)
#define SM_W2HI (2 * TILE_B)
#define SM_W2LO (3 * TILE_B)
#define SM_AHI  (4 * TILE_B)              // A tile (pv split), then H tile
#define SM_ALO  (5 * TILE_B)
#define SM_B2   (6 * TILE_B)              // 512 B
#define SMEM_TOTAL (6 * TILE_B + 512)

// fused 3-term split GEMM for a 32x32 warp tile:
// acc += Ahi*Bhi + Alo*Bhi + Ahi*Blo  (K=128)
__device__ __forceinline__ void gemm3(uint32_t AhiB, uint32_t AloB,
                                      uint32_t BhiB, uint32_t BloB,
                                      int r0, int c0, int lane,
                                      float acc[2][4][4]) {
    const uint32_t rsel = (uint32_t)(lane & 15);
    const uint32_t ksel = (uint32_t)(lane >> 4) * 16;
    const uint32_t aoff = (r0 + rsel) * STRB + ksel;
    const uint32_t boff = (c0 + rsel) * STRB + ksel;
    uint32_t ah0 = AhiB + aoff, ah1 = ah0 + 16 * STRB;
    uint32_t al0 = AloB + aoff, al1 = al0 + 16 * STRB;
    uint32_t bh0 = BhiB + boff, bh1 = bh0 + 16 * STRB;
    uint32_t bl0 = BloB + boff, bl1 = bl0 + 16 * STRB;
#pragma unroll
    for (int kc = 0; kc < 8; kc++) {
        const uint32_t kb = kc * 32;
        uint32_t Ah0[4], Ah1[4], Al0[4], Al1[4];
        uint32_t Bh0[4], Bh1[4], Bl0[4], Bl1[4];
        ldsm4(ah0 + kb, Ah0); ldsm4(ah1 + kb, Ah1);
        ldsm4(bh0 + kb, Bh0); ldsm4(bh1 + kb, Bh1);
        ldsm4(al0 + kb, Al0); ldsm4(al1 + kb, Al1);
        ldsm4(bl0 + kb, Bl0); ldsm4(bl1 + kb, Bl1);
        mma16816(acc[0][0], Ah0, Bh0[0], Bh0[2]);
        mma16816(acc[0][1], Ah0, Bh0[1], Bh0[3]);
        mma16816(acc[0][2], Ah0, Bh1[0], Bh1[2]);
        mma16816(acc[0][3], Ah0, Bh1[1], Bh1[3]);
        mma16816(acc[1][0], Ah1, Bh0[0], Bh0[2]);
        mma16816(acc[1][1], Ah1, Bh0[1], Bh0[3]);
        mma16816(acc[1][2], Ah1, Bh1[0], Bh1[2]);
        mma16816(acc[1][3], Ah1, Bh1[1], Bh1[3]);
        mma16816(acc[0][0], Al0, Bh0[0], Bh0[2]);
        mma16816(acc[0][1], Al0, Bh0[1], Bh0[3]);
        mma16816(acc[0][2], Al0, Bh1[0], Bh1[2]);
        mma16816(acc[0][3], Al0, Bh1[1], Bh1[3]);
        mma16816(acc[1][0], Al1, Bh0[0], Bh0[2]);
        mma16816(acc[1][1], Al1, Bh0[1], Bh0[3]);
        mma16816(acc[1][2], Al1, Bh1[0], Bh1[2]);
        mma16816(acc[1][3], Al1, Bh1[1], Bh1[3]);
        mma16816(acc[0][0], Ah0, Bl0[0], Bl0[2]);
        mma16816(acc[0][1], Ah0, Bl0[1], Bl0[3]);
        mma16816(acc[0][2], Ah0, Bl1[0], Bl1[2]);
        mma16816(acc[0][3], Ah0, Bl1[1], Bl1[3]);
        mma16816(acc[1][0], Ah1, Bl0[0], Bl0[2]);
        mma16816(acc[1][1], Ah1, Bl0[1], Bl0[3]);
        mma16816(acc[1][2], Ah1, Bl1[0], Bl1[2]);
        mma16816(acc[1][3], Ah1, Bl1[1], Bl1[3]);
    }
}

// ---------------- prep: weight splits + cpre + roots + flags ----------------
__global__ __launch_bounds__(256) void prep_kernel(
    const float* __restrict__ emb, const float* __restrict__ emb_table,
    const float* __restrict__ W1, const float* __restrict__ b1,
    const float* __restrict__ W2, float* __restrict__ out) {
    __shared__ float sne[32][64];
    __shared__ float sw[64][128];
    const int blk = blockIdx.x, tid = threadIdx.x;

    if (blk < 128) {
        int n = blk;
        for (int k = tid; k < 128; k += 256) {
            float v = W1[n * 192 + k];
            __nv_bfloat16 h = __float2bfloat16(v);
            g_w1hi[n * HID + k] = h;
            g_w1lo[n * HID + k] = __float2bfloat16(v - __bfloat162float(h));
            float v2 = W2[n * HID + k];
            __nv_bfloat16 h2 = __float2bfloat16(v2);
            g_w2hi[n * HID + k] = h2;
            g_w2lo[n * HID + k] = __float2bfloat16(v2 - __bfloat162float(h2));
        }
        int g = n * 256 + tid;
        if (g < NB * HID) {
            int b = g >> 7, c = g & 127;
            out[(size_t)b * ROWS_PER_B * HID + c] = emb[g];   // root row 0
        }
        if (n == 0) {
            for (int i = tid; i < NFLAGS; i += 256)
                g_flag[i] = (i == 0) ? 4u : 0u;
        }
    }

    const int row0 = blk * 32;
    for (int i = tid; i < 32 * 64; i += 256) {
        int r = i >> 6, e = i & 63;
        sne[r][e] = emb_table[(size_t)(2 + row0 + r) * 64 + e];
    }
    for (int i = tid; i < 128 * 64; i += 256) {
        int c = i >> 6, k = i & 63;
        sw[k][c] = W1[c * 192 + 128 + k];
    }
    __syncthreads();
    int c = tid & 127;
    int rh = (tid >> 7) * 16;
    float acc[16];
    float bv = b1[c];
#pragma unroll
    for (int rr = 0; rr < 16; rr++) acc[rr] = bv;
    for (int k = 0; k < 64; k++) {
        float w = sw[k][c];
#pragma unroll
        for (int rr = 0; rr < 16; rr++) acc[rr] += sne[rh + rr][k] * w;
    }
#pragma unroll
    for (int rr = 0; rr < 16; rr++)
        g_cpre[(size_t)(row0 + rh + rr) * HID + c] = acc[rr];
}

// ---------------- persistent DAG kernel: 4 autonomous warpgroups, no mirror ----------------
__global__ __launch_bounds__(NTHREADS, 1)
void dag_kernel(float* __restrict__ out, const int* __restrict__ pidx,
                const float* __restrict__ b2) {
    extern __shared__ char smc[];
    const uint32_t sb = smem_u32(smc);
    const int tid = threadIdx.x;
    const int wid = tid >> 5, lane = tid & 31;
    const int n0 = blockIdx.x * 4;

    const int nn = wid >> 2;            // warpgroup = node index within CTA
    const int cw = wid & 3;             // warp-in-group = column group
    const int node = n0 + nn;
    const int r0 = nn * 32;
    const int c0 = cw * 32;
    const int bbase = cw * 8;
    const int barid = 1 + nn;
    const int tq = lane >> 2;
    const int tc = (lane & 3) * 2;

    // one-time: stationary W1/W2 tiles + b2
    {
        const uint2* w1h = (const uint2*)g_w1hi;
        const uint2* w1l = (const uint2*)g_w1lo;
        const uint2* w2h = (const uint2*)g_w2hi;
        const uint2* w2l = (const uint2*)g_w2lo;
        for (int i = tid; i < 128 * 32; i += NTHREADS) {
            int r = i >> 5, q = i & 31;
            uint32_t off = (uint32_t)r * STRB + q * 8;
            *(uint2*)(smc + SM_W1HI + off) = w1h[i];
            *(uint2*)(smc + SM_W1LO + off) = w1l[i];
            *(uint2*)(smc + SM_W2HI + off) = w2h[i];
            *(uint2*)(smc + SM_W2LO + off) = w2l[i];
        }
        if (tid < 128) ((float*)(smc + SM_B2))[tid] = b2[tid];
    }
    __syncthreads();
    const float* s_b2 = (const float*)(smc + SM_B2);

    // pidx for depth 0 (hoisted; subsequent depths loaded before bar4)
    int s_par = (lane < NPAR) ? __ldg(&pidx[node * NPAR + lane]) : 0;

    for (int d = 0; d < DEPTH; d++) {
        const int orow = 1 + d * NODES + node;

        // ---- gather from out (batch-major): poll flags, sum, split -> A tiles ----
        {
            int prow = -1;
            if (lane < NPAR) {
                prow = s_par ? (s_par - 1) : -1;
                if (prow >= 0) {
                    volatile unsigned* f = &g_flag[prow];
                    while (*f < 4u) __nanosleep(32);
                }
            }
            __syncwarp();      // rows written-once => no stale L1 possible
            float vx[8], vy[8], vz[8], vw[8];
#pragma unroll
            for (int rr = 0; rr < 8; rr++) { vx[rr] = 0.f; vy[rr] = 0.f; vz[rr] = 0.f; vw[rr] = 0.f; }
#pragma unroll
            for (int p = 0; p < NPAR; p++) {
                int row = __shfl_sync(0xFFFFFFFFu, prow, p);
                if (row < 0) continue;          // warp-uniform skip
                const float* pb = out + ((size_t)bbase * ROWS_PER_B + row) * HID + lane * 4;
#pragma unroll
                for (int rr = 0; rr < 8; rr++) {
                    float4 v = *(const float4*)(pb + (size_t)rr * ROWS_PER_B * HID);
                    vx[rr] += v.x; vy[rr] += v.y; vz[rr] += v.z; vw[rr] += v.w;
                }
            }
#pragma unroll
            for (int rr = 0; rr < 8; rr++) {
                int r = r0 + bbase + rr;
                uint32_t h0, l0, h1, l1;
                split2(vx[rr], vy[rr], h0, l0);
                split2(vz[rr], vw[rr], h1, l1);
                uint32_t o = (uint32_t)r * STRB + lane * 8;
                *(uint32_t*)(smc + SM_AHI + o) = h0;
                *(uint32_t*)(smc + SM_AHI + o + 4) = h1;
                *(uint32_t*)(smc + SM_ALO + o) = l0;
                *(uint32_t*)(smc + SM_ALO + o + 4) = l1;
            }
        }
        named_bar(barid);      // bar1: A tile (pv split) visible within group

        float acc[2][4][4];
#pragma unroll
        for (int mt = 0; mt < 2; mt++)
#pragma unroll
            for (int nt = 0; nt < 4; nt++)
#pragma unroll
                for (int q = 0; q < 4; q++) acc[mt][nt][q] = 0.f;

        // ---- GEMM1: A x W1 ----
        gemm3(sb + SM_AHI, sb + SM_ALO, sb + SM_W1HI, sb + SM_W1LO, r0, c0, lane, acc);

        // ---- seed GEMM2 accumulator with pv (from A tiles) + b2 ----
        float acc2[2][4][4];
#pragma unroll
        for (int nt = 0; nt < 4; nt++) {
            int c = c0 + nt * 8 + tc;
            float2 b2v = *(const float2*)(s_b2 + c);
#pragma unroll
            for (int mt = 0; mt < 2; mt++) {
#pragma unroll
                for (int half = 0; half < 2; half++) {
                    int b = mt * 16 + tq + half * 8;
                    int rA = r0 + b;
                    uint32_t off = (uint32_t)rA * STRB + c * 2;
                    float2 pvv = unsplit2(*(const uint32_t*)(smc + SM_AHI + off),
                                          *(const uint32_t*)(smc + SM_ALO + off));
                    acc2[mt][nt][half * 2 + 0] = pvv.x + b2v.x;
                    acc2[mt][nt][half * 2 + 1] = pvv.y + b2v.y;
                }
            }
        }
        named_bar(barid);      // bar2: all A reads (GEMM1 + seed) done

        // ---- relu(D1 + cpre) -> split -> H (A region) ----
        {
            const float* cp = g_cpre + (size_t)(d * NODES + node) * HID;
#pragma unroll
            for (int mt = 0; mt < 2; mt++) {
#pragma unroll
                for (int nt = 0; nt < 4; nt++) {
                    int c = c0 + nt * 8 + tc;
                    float2 cpv = *(const float2*)(cp + c);
                    float v0 = fmaxf(acc[mt][nt][0] + cpv.x, 0.f);
                    float v1 = fmaxf(acc[mt][nt][1] + cpv.y, 0.f);
                    float v2 = fmaxf(acc[mt][nt][2] + cpv.x, 0.f);
                    float v3 = fmaxf(acc[mt][nt][3] + cpv.y, 0.f);
                    uint32_t hi, lo;
                    uint32_t oA = (uint32_t)(r0 + mt * 16 + tq) * STRB + c * 2;
                    uint32_t oB = oA + 8 * STRB;
                    split2(v0, v1, hi, lo);
                    *(uint32_t*)(smc + SM_AHI + oA) = hi;
                    *(uint32_t*)(smc + SM_ALO + oA) = lo;
                    split2(v2, v3, hi, lo);
                    *(uint32_t*)(smc + SM_AHI + oB) = hi;
                    *(uint32_t*)(smc + SM_ALO + oB) = lo;
                }
            }
        }
        named_bar(barid);      // bar3: H visible within group

        // ---- GEMM2: acc2(pv + b2) += H x W2 ----
        gemm3(sb + SM_AHI, sb + SM_ALO, sb + SM_W2HI, sb + SM_W2LO, r0, c0, lane, acc2);

        // ---- epilogue: single store to out; publish; prefetch next pidx ----
#pragma unroll
        for (int mt = 0; mt < 2; mt++) {
#pragma unroll
            for (int half = 0; half < 2; half++) {
                int b = mt * 16 + tq + half * 8;
                float* po = out + ((size_t)b * ROWS_PER_B + orow) * HID;
#pragma unroll
                for (int nt = 0; nt < 4; nt++) {
                    int c = c0 + nt * 8 + tc;
                    *(float2*)(po + c) = make_float2(acc2[mt][nt][half * 2 + 0],
                                                     acc2[mt][nt][half * 2 + 1]);
                }
            }
        }
        if (d + 1 < DEPTH) {
            __syncwarp();
            if (lane == 0) red_release_add(&g_flag[orow], 1u);
            if (lane < NPAR)
                s_par = __ldg(&pidx[((d + 1) * NODES + node) * NPAR + lane]);
            named_bar(barid);      // bar4: group GEMM2 reads done; A/H reusable
        }
    }
}

extern "C" void kernel_launch(void* const* d_in, const int* in_sizes, int n_in,
                              void* d_out, int out_size) {
    const float* embedding  = (const float*)d_in[0];
    const float* emb_table  = (const float*)d_in[1];
    const float* W1         = (const float*)d_in[2];
    const float* b1         = (const float*)d_in[3];
    const float* W2         = (const float*)d_in[4];
    const float* b2         = (const float*)d_in[5];
    const int*   parent_idx = (const int*)d_in[6];
    float* out = (float*)d_out;
    (void)in_sizes; (void)n_in; (void)out_size;

    cudaFuncSetAttribute(dag_kernel,
                         cudaFuncAttributeMaxDynamicSharedMemorySize, SMEM_TOTAL);

    prep_kernel<<<DEPTH * NODES / 32, 256>>>(embedding, emb_table, W1, b1, W2, out);
    dag_kernel<<<128, NTHREADS, SMEM_TOTAL>>>(out, parent_idx, b2);
}